// round 10
// baseline (speedup 1.0000x reference)
#include <cuda_runtime.h>
#include <cuda_bf16.h>
#include <cstddef>
#include <cstdint>

#define WB     1024
#define NTOK   128
#define NHEADS 8
#define HD     16
#define MROWS  (WB * NTOK)          // 131072

typedef unsigned long long ull;
typedef unsigned short ush;

// ---------------- scratch (device globals; no runtime allocation) ----------
__device__ ush g_xs3  [(size_t)MROWS * 384];
__device__ ush g_xpes3[(size_t)MROWS * 384];
__device__ ush g_ws3  [384 * 384];
__device__ ush g_wm3  [384 * 384];
__device__ ush g_wp3  [128 * 768];
__device__ float g_qkv_self[(size_t)MROWS * 384];
__device__ float g_qkv_mut [(size_t)MROWS * 384];
__device__ ush g_concat3[(size_t)MROWS * 768];
__device__ float g_mbias[(size_t)NHEADS * 512 * NTOK * NTOK]; // [h][w][i][m]

__device__ __forceinline__ void split_hl(float v, ush& h, ush& l) {
    __nv_bfloat16 hh = __float2bfloat16(v);
    float r = v - __bfloat162float(hh);
    __nv_bfloat16 ll = __float2bfloat16(r);
    h = *(ush*)&hh;
    l = *(ush*)&ll;
}

// pack two A-side triplets (h,h,l)(h,h,l) -> 3 uint32
__device__ __forceinline__ void trip2(float a, float b, unsigned* o) {
    ush h0, l0, h1, l1;
    split_hl(a, h0, l0); split_hl(b, h1, l1);
    o[0] = (unsigned)h0 | ((unsigned)h0 << 16);
    o[1] = (unsigned)l0 | ((unsigned)h1 << 16);
    o[2] = (unsigned)h1 | ((unsigned)l1 << 16);
}

// ---------------- fused prep (ONE launch) -----------------------------------
// blocks [0,512):      weight split (B-side h,l,h)
// blocks [512,8704):   x split (A-side h,h,l) + x+pe split
// blocks [8704,16896): mbias[h][w][i][m] = mask[w][i][m] + rpe_table[idx[i][m]][h]
__global__ void __launch_bounds__(256) prep_all(
    const float* __restrict__ x, const float* __restrict__ pe,
    const float* __restrict__ ws, const float* __restrict__ wm,
    const float* __restrict__ wp, const float* __restrict__ mask,
    const int* __restrict__ rpe_index, const float* __restrict__ rpe_table)
{
    const int bid = blockIdx.x, tid = threadIdx.x;
    if (bid < 512) {
        int i = bid * 256 + tid;
        float v; ush* dst;
        if (i < 49152)       { v = ws[i];          dst = g_ws3 + 3 * i; }
        else if (i < 98304)  { v = wm[i - 49152];  dst = g_wm3 + 3 * (i - 49152); }
        else                 { v = wp[i - 98304];  dst = g_wp3 + 3 * (i - 98304); }
        ush h, l;
        split_hl(v, h, l);
        dst[0] = h; dst[1] = l; dst[2] = h;
        return;
    }
    if (bid < 8704) {
        size_t idx8 = (size_t)(bid - 512) * 256 + tid;
        size_t e0 = idx8 * 8;
        int c = (int)(e0 & 127);
        int t = (int)((e0 >> 7) & 127);
        float4 xv0 = ((const float4*)x)[idx8 * 2];
        float4 xv1 = ((const float4*)x)[idx8 * 2 + 1];
        const float* pp = pe + (t & 63) * 128 + c;
        float xe[8] = {xv0.x, xv0.y, xv0.z, xv0.w, xv1.x, xv1.y, xv1.z, xv1.w};
        ush b0[24], b1[24];
#pragma unroll
        for (int j = 0; j < 8; ++j) {
            ush h, l;
            split_hl(xe[j], h, l);
            b0[3 * j] = h; b0[3 * j + 1] = h; b0[3 * j + 2] = l;
            split_hl(xe[j] + pp[j], h, l);
            b1[3 * j] = h; b1[3 * j + 1] = h; b1[3 * j + 2] = l;
        }
        uint4* d0 = (uint4*)(g_xs3 + 3 * e0);
        uint4* d1 = (uint4*)(g_xpes3 + 3 * e0);
        const uint4* s0 = (const uint4*)b0;
        const uint4* s1 = (const uint4*)b1;
        d0[0] = s0[0]; d0[1] = s0[1]; d0[2] = s0[2];
        d1[0] = s1[0]; d1[1] = s1[1]; d1[2] = s1[2];
        return;
    }
    {
        int blin = bid - 8704;                   // 0..8191
        int w = blin >> 4;
        int i0 = (blin & 15) * 8;
        int m = tid & 127;
#pragma unroll
        for (int jj = 0; jj < 4; ++jj) {
            int i = i0 + (tid >> 7) + jj * 2;
            float mval = mask[(size_t)w * 16384 + i * 128 + m];
            int tix = rpe_index[i * 128 + m];
            const float* rt = rpe_table + tix * 8;
            float2 r01 = *(const float2*)(rt);
            float2 r23 = *(const float2*)(rt + 2);
            float2 r45 = *(const float2*)(rt + 4);
            float2 r67 = *(const float2*)(rt + 6);
            float rv[8] = {r01.x, r01.y, r23.x, r23.y, r45.x, r45.y, r67.x, r67.y};
            size_t o = ((size_t)w * 128 + i) * 128 + m;
#pragma unroll
            for (int h = 0; h < NHEADS; ++h)
                g_mbias[(size_t)h * 512 * 16384 + o] = mval + rv[h];
        }
    }
}

// ---------------- bf16-split tensor-core GEMM (3-stage pipeline) -----------
#define MMA_BF16(d, a, b0r, b1r) \
    asm volatile("mma.sync.aligned.m16n8k16.row.col.f32.bf16.bf16.f32 " \
        "{%0,%1,%2,%3},{%4,%5,%6,%7},{%8,%9},{%0,%1,%2,%3};" \
        : "+f"(d[0]), "+f"(d[1]), "+f"(d[2]), "+f"(d[3]) \
        : "r"(a[0]), "r"(a[1]), "r"(a[2]), "r"(a[3]), "r"(b0r), "r"(b1r))

#define LDSM4(r0, r1, r2, r3, addr) \
    asm volatile("ldmatrix.sync.aligned.m8n8.x4.shared.b16 {%0,%1,%2,%3}, [%4];" \
        : "=r"(r0), "=r"(r1), "=r"(r2), "=r"(r3) : "r"(addr))

#define CP16(dst, src) \
    asm volatile("cp.async.cg.shared.global [%0], [%1], 16;" :: "r"(dst), "l"(src))

#define PITCH 72
#define STAGE_ELEMS (128 * PITCH)
#define NSTAGE 3

template<int KTOT, int NTOT, bool BIAS>
__global__ void __launch_bounds__(256) gemm_bf16(
    const __nv_bfloat16* __restrict__ A, const __nv_bfloat16* __restrict__ W,
    const float* __restrict__ bvec, float* __restrict__ C)
{
    extern __shared__ __nv_bfloat16 smem[];
    __nv_bfloat16* As = smem;
    __nv_bfloat16* Bs = smem + NSTAGE * STAGE_ELEMS;

    const int tid = threadIdx.x;
    const int lane = tid & 31, wid = tid >> 5;
    const int wm = (wid & 1) * 64, wn = (wid >> 1) * 32;
    const int g = lane >> 2, tg = lane & 3;
    const size_t row0 = (size_t)blockIdx.y * 128;
    const int col0 = blockIdx.x * 128;
    constexpr int NC = KTOT / 64;

    const int ldr = tid >> 1;
    const int ldu = (tid & 1) * 4;

    float acc[4][4][4] = {};

    const int a_row = wm + (lane & 15);
    const int a_col = (lane >> 4) * 8;
    const int bq = lane >> 3;
    const int b_row = wn + ((bq >> 1) * 8) + (lane & 7);
    const int b_col = (bq & 1) * 8;

#define LOAD_STAGE(kc, s)                                                        \
    {                                                                            \
        const __nv_bfloat16* Ab = A + (row0 + ldr) * KTOT + (kc) * 64;           \
        const __nv_bfloat16* Wb = W + (size_t)(col0 + ldr) * KTOT + (kc) * 64;   \
        __nv_bfloat16* Ad = As + (s) * STAGE_ELEMS + ldr * PITCH;                \
        __nv_bfloat16* Bd = Bs + (s) * STAGE_ELEMS + ldr * PITCH;                \
        _Pragma("unroll")                                                        \
        for (int u = 0; u < 4; ++u) {                                            \
            unsigned da = (unsigned)__cvta_generic_to_shared(Ad + (ldu + u) * 8);\
            CP16(da, Ab + (ldu + u) * 8);                                        \
            unsigned db = (unsigned)__cvta_generic_to_shared(Bd + (ldu + u) * 8);\
            CP16(db, Wb + (ldu + u) * 8);                                        \
        }                                                                        \
        asm volatile("cp.async.commit_group;");                                  \
    }

    LOAD_STAGE(0, 0);
    LOAD_STAGE(1, 1);

#pragma unroll
    for (int kc = 0; kc < NC; ++kc) {
        const int cur = kc % NSTAGE;
        if (kc + 2 < NC) {
            asm volatile("cp.async.wait_group 1;");
        } else {
            asm volatile("cp.async.wait_group 0;");
        }
        __syncthreads();
        if (kc + 2 < NC) LOAD_STAGE(kc + 2, (kc + 2) % NSTAGE);

        const __nv_bfloat16* Ad = As + cur * STAGE_ELEMS;
        const __nv_bfloat16* Bd = Bs + cur * STAGE_ELEMS;
#pragma unroll
        for (int ks = 0; ks < 4; ++ks) {
            const int kb = ks * 16;
            uint32_t a[4][4], b[2][4];
#pragma unroll
            for (int mt = 0; mt < 4; ++mt) {
                unsigned ad = (unsigned)__cvta_generic_to_shared(
                    Ad + (a_row + mt * 16) * PITCH + kb + a_col);
                LDSM4(a[mt][0], a[mt][1], a[mt][2], a[mt][3], ad);
            }
#pragma unroll
            for (int p = 0; p < 2; ++p) {
                unsigned bd = (unsigned)__cvta_generic_to_shared(
                    Bd + (b_row + p * 16) * PITCH + kb + b_col);
                LDSM4(b[p][0], b[p][1], b[p][2], b[p][3], bd);
            }
#pragma unroll
            for (int mt = 0; mt < 4; ++mt)
#pragma unroll
                for (int nt = 0; nt < 4; ++nt)
                    MMA_BF16(acc[mt][nt], a[mt], b[nt >> 1][(nt & 1) * 2],
                             b[nt >> 1][(nt & 1) * 2 + 1]);
        }
        __syncthreads();
    }

#pragma unroll
    for (int mt = 0; mt < 4; ++mt) {
#pragma unroll
        for (int nt = 0; nt < 4; ++nt) {
            size_t row = row0 + wm + mt * 16 + g;
            int col = col0 + wn + nt * 8 + 2 * tg;
            float b0 = BIAS ? bvec[col] : 0.f, b1 = BIAS ? bvec[col + 1] : 0.f;
            *(float2*)&C[row * NTOT + col] =
                make_float2(acc[mt][nt][0] + b0, acc[mt][nt][1] + b1);
            *(float2*)&C[(row + 8) * NTOT + col] =
                make_float2(acc[mt][nt][2] + b0, acc[mt][nt][3] + b1);
        }
    }
}

// ---------------- tensor-core attention --------------------------------------
// blockIdx.y < 8: self-attention head y; >= 8: mutual head y-8.
// 128 threads = 4 warps, each warp owns 32 query rows.
// Q: A-side split K'=48 (pre-scaled 0.25); K: B-side split; V^T: B-side split.
// smem: Qs[128][56] Ks[128][56] Vt[16][392] Ps[4][32][104]
#define PQ 56
#define PV 392
#define PP 104
#define ATTN_SMEM ((2 * 128 * PQ + 16 * PV + 4 * 32 * PP) * 2)

__global__ void __launch_bounds__(128) attn_tc(const float* __restrict__ mask)
{
    extern __shared__ __nv_bfloat16 sm[];
    __nv_bfloat16* Qs = sm;
    __nv_bfloat16* Ks = sm + 128 * PQ;
    __nv_bfloat16* Vt = sm + 2 * 128 * PQ;
    __nv_bfloat16* Ps0 = Vt + 16 * PV;

    const int b = blockIdx.x;
    const bool self = blockIdx.y < 8;
    const int h = self ? blockIdx.y : blockIdx.y - 8;
    const int tid = threadIdx.x, lane = tid & 31, wid = tid >> 5;
    const float* base = (self ? g_qkv_self : g_qkv_mut) + (size_t)b * NTOK * 384;

    // ---- convert Q, K, V into smem ----
    {
        int qrow = self ? tid : ((tid < 64) ? 64 + tid : tid - 64);
        const float* qp = base + qrow * 384 + h * HD;
        ush buf[48];
#pragma unroll
        for (int j = 0; j < 16; ++j) {
            ush hh, ll;
            split_hl(qp[j] * 0.25f, hh, ll);
            buf[3 * j] = hh; buf[3 * j + 1] = hh; buf[3 * j + 2] = ll;
        }
        uint4* qd = (uint4*)(Qs + tid * PQ);
        const uint4* s = (const uint4*)buf;
#pragma unroll
        for (int u = 0; u < 6; ++u) qd[u] = s[u];

        const float* kp = base + tid * 384 + 128 + h * HD;
#pragma unroll
        for (int j = 0; j < 16; ++j) {
            ush hh, ll;
            split_hl(kp[j], hh, ll);
            buf[3 * j] = hh; buf[3 * j + 1] = ll; buf[3 * j + 2] = hh;
        }
        uint4* kd = (uint4*)(Ks + tid * PQ);
#pragma unroll
        for (int u = 0; u < 6; ++u) kd[u] = s[u];

        const float* vp = base + tid * 384 + 256 + h * HD;
#pragma unroll
        for (int d = 0; d < 16; ++d) {
            ush hh, ll;
            split_hl(vp[d], hh, ll);
            __nv_bfloat16* vd = Vt + d * PV + 3 * tid;
            vd[0] = *(__nv_bfloat16*)&hh;
            vd[1] = *(__nv_bfloat16*)&ll;
            vd[2] = *(__nv_bfloat16*)&hh;
        }
    }
    __syncthreads();

    const int g = lane >> 2, tg = lane & 3;
    const int r0 = wid * 32;
    const int a_row = lane & 15, a_col = (lane >> 4) * 8;
    const int bq = lane >> 3;
    const int b_rsub = ((bq >> 1) * 8) + (lane & 7);
    const int b_col8 = (bq & 1) * 8;
    __nv_bfloat16* Ps = Ps0 + wid * 32 * PP;

    const int nchunk = self ? 4 : 2;
    const int kb0 = (self || wid < 2) ? 0 : 64;
    const float* mbA_base = self
        ? g_mbias + ((size_t)h * 512 + (b & 511)) * 16384
        : mask + (size_t)(b & 511) * 16384;

    float accO[2][2][4] = {};
    float rs[4] = {0.f, 0.f, 0.f, 0.f};

    for (int mc = 0; mc < nchunk; ++mc) {
        const int key0 = kb0 + mc * 32;
        // ---- scores: S[32, 32] = Qs[r0..][48] @ Ks[key0..][48]^T ----
        float accS[2][4][4] = {};
#pragma unroll
        for (int kt = 0; kt < 3; ++kt) {
            uint32_t a[2][4], bf[2][4];
#pragma unroll
            for (int mt = 0; mt < 2; ++mt) {
                unsigned ad = (unsigned)__cvta_generic_to_shared(
                    Qs + (r0 + mt * 16 + a_row) * PQ + kt * 16 + a_col);
                LDSM4(a[mt][0], a[mt][1], a[mt][2], a[mt][3], ad);
            }
#pragma unroll
            for (int p = 0; p < 2; ++p) {
                unsigned bd = (unsigned)__cvta_generic_to_shared(
                    Ks + (key0 + p * 16 + b_rsub) * PQ + kt * 16 + b_col8);
                LDSM4(bf[p][0], bf[p][1], bf[p][2], bf[p][3], bd);
            }
#pragma unroll
            for (int mt = 0; mt < 2; ++mt)
#pragma unroll
                for (int nt = 0; nt < 4; ++nt)
                    MMA_BF16(accS[mt][nt], a[mt], bf[nt >> 1][(nt & 1) * 2],
                             bf[nt >> 1][(nt & 1) * 2 + 1]);
        }
        // ---- bias + exp + split-store P + row-sum partials ----
#pragma unroll
        for (int mt = 0; mt < 2; ++mt) {
            const int rA = r0 + mt * 16 + g;
            const float* mrA = mbA_base + (self ? rA : (rA & 63)) * 128;
            const float* mrB = mbA_base + (self ? (rA + 8) : ((rA + 8) & 63)) * 128;
#pragma unroll
            for (int nt = 0; nt < 4; ++nt) {
                const int ml = (self ? key0 : mc * 32) + nt * 8 + 2 * tg;
                float2 mA = *(const float2*)(mrA + ml);
                float2 mB = *(const float2*)(mrB + ml);
                float p0 = __expf(accS[mt][nt][0] + mA.x);
                float p1 = __expf(accS[mt][nt][1] + mA.y);
                float p2 = __expf(accS[mt][nt][2] + mB.x);
                float p3 = __expf(accS[mt][nt][3] + mB.y);
                rs[2 * mt]     += p0 + p1;
                rs[2 * mt + 1] += p2 + p3;
                unsigned tb[3];
                trip2(p0, p1, tb);
                unsigned* dA = (unsigned*)(Ps + (mt * 16 + g) * PP + 24 * nt + 6 * tg);
                dA[0] = tb[0]; dA[1] = tb[1]; dA[2] = tb[2];
                trip2(p2, p3, tb);
                unsigned* dB = (unsigned*)(Ps + (mt * 16 + g + 8) * PP + 24 * nt + 6 * tg);
                dB[0] = tb[0]; dB[1] = tb[1]; dB[2] = tb[2];
            }
        }
        __syncwarp();
        // ---- PV: O[32,16] += P[32, 96] @ Vt[16, key0*3 + 96]^T ----
#pragma unroll
        for (int kt2 = 0; kt2 < 6; ++kt2) {
            uint32_t a2[2][4], b2[4];
#pragma unroll
            for (int mt = 0; mt < 2; ++mt) {
                unsigned ad = (unsigned)__cvta_generic_to_shared(
                    Ps + (mt * 16 + a_row) * PP + kt2 * 16 + a_col);
                LDSM4(a2[mt][0], a2[mt][1], a2[mt][2], a2[mt][3], ad);
            }
            {
                unsigned bd = (unsigned)__cvta_generic_to_shared(
                    Vt + b_rsub * PV + key0 * 3 + kt2 * 16 + b_col8);
                LDSM4(b2[0], b2[1], b2[2], b2[3], bd);
            }
#pragma unroll
            for (int mt = 0; mt < 2; ++mt)
#pragma unroll
                for (int nt2 = 0; nt2 < 2; ++nt2)
                    MMA_BF16(accO[mt][nt2], a2[mt], b2[nt2 * 2], b2[nt2 * 2 + 1]);
        }
        __syncwarp();
    }

    // ---- row-sum reduce over the tg quad ----
#pragma unroll
    for (int s = 0; s < 4; ++s) {
        rs[s] += __shfl_xor_sync(0xffffffffu, rs[s], 1);
        rs[s] += __shfl_xor_sync(0xffffffffu, rs[s], 2);
    }
    float inv[4];
#pragma unroll
    for (int s = 0; s < 4; ++s) inv[s] = 1.f / rs[s];

    // ---- write O (split triplets) to g_concat3 ----
    const int cbase = self ? 384 : 0;    // (128 cols) * 3 for self half
#pragma unroll
    for (int mt = 0; mt < 2; ++mt) {
#pragma unroll
        for (int nt2 = 0; nt2 < 2; ++nt2) {
            const int d0 = nt2 * 8 + 2 * tg;
            const int rA = r0 + mt * 16 + g;
            unsigned tb[3];
            trip2(accO[mt][nt2][0] * inv[2 * mt], accO[mt][nt2][1] * inv[2 * mt], tb);
            unsigned* oA = (unsigned*)(g_concat3 +
                ((size_t)b * NTOK + rA) * 768 + cbase + (h * HD + d0) * 3);
            oA[0] = tb[0]; oA[1] = tb[1]; oA[2] = tb[2];
            trip2(accO[mt][nt2][2] * inv[2 * mt + 1], accO[mt][nt2][3] * inv[2 * mt + 1], tb);
            unsigned* oB = (unsigned*)(g_concat3 +
                ((size_t)b * NTOK + rA + 8) * 768 + cbase + (h * HD + d0) * 3);
            oB[0] = tb[0]; oB[1] = tb[1]; oB[2] = tb[2];
        }
    }
}

// ---------------- launch ----------------------------------------------------
extern "C" void kernel_launch(void* const* d_in, const int* in_sizes, int n_in,
                              void* d_out, int out_size)
{
    const float* x         = (const float*)d_in[0];
    const float* mask      = (const float*)d_in[1];
    const float* w_self    = (const float*)d_in[2];
    const float* w_mut     = (const float*)d_in[3];
    const float* w_proj    = (const float*)d_in[4];
    const float* b_proj    = (const float*)d_in[5];
    const float* rpe_table = (const float*)d_in[6];
    const float* pe        = (const float*)d_in[7];
    const int*   rpe_index = (const int*)d_in[8];
    float* out = (float*)d_out;

    ush *xs, *xpes, *cc, *ws, *wm, *wp;
    float *qs, *qm;
    cudaGetSymbolAddress((void**)&ws, g_ws3);
    cudaGetSymbolAddress((void**)&wm, g_wm3);
    cudaGetSymbolAddress((void**)&wp, g_wp3);
    cudaGetSymbolAddress((void**)&xs, g_xs3);
    cudaGetSymbolAddress((void**)&xpes, g_xpes3);
    cudaGetSymbolAddress((void**)&qs, g_qkv_self);
    cudaGetSymbolAddress((void**)&qm, g_qkv_mut);
    cudaGetSymbolAddress((void**)&cc, g_concat3);

    const int SMEM = 2 * NSTAGE * STAGE_ELEMS * (int)sizeof(__nv_bfloat16); // 110592
    cudaFuncSetAttribute(gemm_bf16<384, 384, false>,
                         cudaFuncAttributeMaxDynamicSharedMemorySize, SMEM);
    cudaFuncSetAttribute(gemm_bf16<768, 128, true>,
                         cudaFuncAttributeMaxDynamicSharedMemorySize, SMEM);
    cudaFuncSetAttribute(attn_tc,
                         cudaFuncAttributeMaxDynamicSharedMemorySize, ATTN_SMEM);

    // launch 1: all prep (weights, x-split, fused mbias)
    prep_all<<<16896, 256>>>(x, pe, w_self, w_mut, w_proj, mask, rpe_index, rpe_table);

    // launches 2,3: QKV GEMMs (K' = 384)
    gemm_bf16<384, 384, false><<<dim3(3, 1024), 256, SMEM>>>(
        (const __nv_bfloat16*)xs,   (const __nv_bfloat16*)ws, nullptr, qs);
    gemm_bf16<384, 384, false><<<dim3(3, 1024), 256, SMEM>>>(
        (const __nv_bfloat16*)xpes, (const __nv_bfloat16*)wm, nullptr, qm);

    // launch 4: tensor-core attention  (<- ncu capture slot)
    attn_tc<<<dim3(WB, 16), 128, ATTN_SMEM>>>(mask);

    // launch 5: projection (K' = 768)
    gemm_bf16<768, 128, true><<<dim3(1, 1024), 256, SMEM>>>(
        (const __nv_bfloat16*)cc, (const __nv_bfloat16*)wp, b_proj, out);
}

// round 11
// speedup vs baseline: 1.0898x; 1.0898x over previous
#include <cuda_runtime.h>
#include <cuda_bf16.h>
#include <cstddef>
#include <cstdint>

#define WB     1024
#define NTOK   128
#define NHEADS 8
#define HD     16
#define MROWS  (WB * NTOK)          // 131072

typedef unsigned long long ull;
typedef unsigned short ush;

// ---------------- scratch (device globals; no runtime allocation) ----------
__device__ ush g_xs3  [(size_t)MROWS * 384];
__device__ ush g_xpes3[(size_t)MROWS * 384];
__device__ ush g_ws3  [384 * 384];
__device__ ush g_wm3  [384 * 384];
__device__ ush g_wp3  [128 * 768];
__device__ float g_qkv_self[(size_t)MROWS * 384];
__device__ float g_qkv_mut [(size_t)MROWS * 384];
__device__ ush g_concat3[(size_t)MROWS * 768];
__device__ float g_mbias[(size_t)NHEADS * 512 * NTOK * NTOK]; // [h][w][i][m]

__device__ __forceinline__ void split_hl(float v, ush& h, ush& l) {
    __nv_bfloat16 hh = __float2bfloat16(v);
    float r = v - __bfloat162float(hh);
    __nv_bfloat16 ll = __float2bfloat16(r);
    h = *(ush*)&hh;
    l = *(ush*)&ll;
}

// pack two A-side triplets (h,h,l)(h,h,l) -> 3 uint32
__device__ __forceinline__ void trip2(float a, float b, unsigned* o) {
    ush h0, l0, h1, l1;
    split_hl(a, h0, l0); split_hl(b, h1, l1);
    o[0] = (unsigned)h0 | ((unsigned)h0 << 16);
    o[1] = (unsigned)l0 | ((unsigned)h1 << 16);
    o[2] = (unsigned)h1 | ((unsigned)l1 << 16);
}

// ---------------- fused prep (ONE launch) -----------------------------------
__global__ void __launch_bounds__(256) prep_all(
    const float* __restrict__ x, const float* __restrict__ pe,
    const float* __restrict__ ws, const float* __restrict__ wm,
    const float* __restrict__ wp, const float* __restrict__ mask,
    const int* __restrict__ rpe_index, const float* __restrict__ rpe_table)
{
    const int bid = blockIdx.x, tid = threadIdx.x;
    if (bid < 512) {
        int i = bid * 256 + tid;
        float v; ush* dst;
        if (i < 49152)       { v = ws[i];          dst = g_ws3 + 3 * i; }
        else if (i < 98304)  { v = wm[i - 49152];  dst = g_wm3 + 3 * (i - 49152); }
        else                 { v = wp[i - 98304];  dst = g_wp3 + 3 * (i - 98304); }
        ush h, l;
        split_hl(v, h, l);
        dst[0] = h; dst[1] = l; dst[2] = h;
        return;
    }
    if (bid < 8704) {
        size_t idx8 = (size_t)(bid - 512) * 256 + tid;
        size_t e0 = idx8 * 8;
        int c = (int)(e0 & 127);
        int t = (int)((e0 >> 7) & 127);
        float4 xv0 = ((const float4*)x)[idx8 * 2];
        float4 xv1 = ((const float4*)x)[idx8 * 2 + 1];
        const float* pp = pe + (t & 63) * 128 + c;
        float xe[8] = {xv0.x, xv0.y, xv0.z, xv0.w, xv1.x, xv1.y, xv1.z, xv1.w};
        ush b0[24], b1[24];
#pragma unroll
        for (int j = 0; j < 8; ++j) {
            ush h, l;
            split_hl(xe[j], h, l);
            b0[3 * j] = h; b0[3 * j + 1] = h; b0[3 * j + 2] = l;
            split_hl(xe[j] + pp[j], h, l);
            b1[3 * j] = h; b1[3 * j + 1] = h; b1[3 * j + 2] = l;
        }
        uint4* d0 = (uint4*)(g_xs3 + 3 * e0);
        uint4* d1 = (uint4*)(g_xpes3 + 3 * e0);
        const uint4* s0 = (const uint4*)b0;
        const uint4* s1 = (const uint4*)b1;
        d0[0] = s0[0]; d0[1] = s0[1]; d0[2] = s0[2];
        d1[0] = s1[0]; d1[1] = s1[1]; d1[2] = s1[2];
        return;
    }
    {
        int blin = bid - 8704;                   // 0..8191
        int w = blin >> 4;
        int i0 = (blin & 15) * 8;
        int m = tid & 127;
#pragma unroll
        for (int jj = 0; jj < 4; ++jj) {
            int i = i0 + (tid >> 7) + jj * 2;
            float mval = mask[(size_t)w * 16384 + i * 128 + m];
            int tix = rpe_index[i * 128 + m];
            const float* rt = rpe_table + tix * 8;
            float2 r01 = *(const float2*)(rt);
            float2 r23 = *(const float2*)(rt + 2);
            float2 r45 = *(const float2*)(rt + 4);
            float2 r67 = *(const float2*)(rt + 6);
            float rv[8] = {r01.x, r01.y, r23.x, r23.y, r45.x, r45.y, r67.x, r67.y};
            size_t o = ((size_t)w * 128 + i) * 128 + m;
#pragma unroll
            for (int h = 0; h < NHEADS; ++h)
                g_mbias[(size_t)h * 512 * 16384 + o] = mval + rv[h];
        }
    }
}

// ---------------- mma / ldsm / cp.async macros ------------------------------
#define MMA_BF16(d, a, b0r, b1r) \
    asm volatile("mma.sync.aligned.m16n8k16.row.col.f32.bf16.bf16.f32 " \
        "{%0,%1,%2,%3},{%4,%5,%6,%7},{%8,%9},{%0,%1,%2,%3};" \
        : "+f"(d[0]), "+f"(d[1]), "+f"(d[2]), "+f"(d[3]) \
        : "r"(a[0]), "r"(a[1]), "r"(a[2]), "r"(a[3]), "r"(b0r), "r"(b1r))

#define MMA_F16(d, a, b0r, b1r) \
    asm volatile("mma.sync.aligned.m16n8k16.row.col.f32.f16.f16.f32 " \
        "{%0,%1,%2,%3},{%4,%5,%6,%7},{%8,%9},{%0,%1,%2,%3};" \
        : "+f"(d[0]), "+f"(d[1]), "+f"(d[2]), "+f"(d[3]) \
        : "r"(a[0]), "r"(a[1]), "r"(a[2]), "r"(a[3]), "r"(b0r), "r"(b1r))

#define LDSM4(r0, r1, r2, r3, addr) \
    asm volatile("ldmatrix.sync.aligned.m8n8.x4.shared.b16 {%0,%1,%2,%3}, [%4];" \
        : "=r"(r0), "=r"(r1), "=r"(r2), "=r"(r3) : "r"(addr))

#define CP16(dst, src) \
    asm volatile("cp.async.cg.shared.global [%0], [%1], 16;" :: "r"(dst), "l"(src))

// d = {hi -> upper half, lo -> lower half}
#define CVT_F16X2(d, hi, lo) \
    asm("cvt.rn.f16x2.f32 %0, %1, %2;" : "=r"(d) : "f"(hi), "f"(lo))

#define PITCH 72
#define STAGE_ELEMS (128 * PITCH)
#define NSTAGE 3

template<int KTOT, int NTOT, bool BIAS>
__global__ void __launch_bounds__(256) gemm_bf16(
    const __nv_bfloat16* __restrict__ A, const __nv_bfloat16* __restrict__ W,
    const float* __restrict__ bvec, float* __restrict__ C)
{
    extern __shared__ __nv_bfloat16 smem[];
    __nv_bfloat16* As = smem;
    __nv_bfloat16* Bs = smem + NSTAGE * STAGE_ELEMS;

    const int tid = threadIdx.x;
    const int lane = tid & 31, wid = tid >> 5;
    const int wm = (wid & 1) * 64, wn = (wid >> 1) * 32;
    const int g = lane >> 2, tg = lane & 3;
    const size_t row0 = (size_t)blockIdx.y * 128;
    const int col0 = blockIdx.x * 128;
    constexpr int NC = KTOT / 64;

    const int ldr = tid >> 1;
    const int ldu = (tid & 1) * 4;

    float acc[4][4][4] = {};

    const int a_row = wm + (lane & 15);
    const int a_col = (lane >> 4) * 8;
    const int bq = lane >> 3;
    const int b_row = wn + ((bq >> 1) * 8) + (lane & 7);
    const int b_col = (bq & 1) * 8;

#define LOAD_STAGE(kc, s)                                                        \
    {                                                                            \
        const __nv_bfloat16* Ab = A + (row0 + ldr) * KTOT + (kc) * 64;           \
        const __nv_bfloat16* Wb = W + (size_t)(col0 + ldr) * KTOT + (kc) * 64;   \
        __nv_bfloat16* Ad = As + (s) * STAGE_ELEMS + ldr * PITCH;                \
        __nv_bfloat16* Bd = Bs + (s) * STAGE_ELEMS + ldr * PITCH;                \
        _Pragma("unroll")                                                        \
        for (int u = 0; u < 4; ++u) {                                            \
            unsigned da = (unsigned)__cvta_generic_to_shared(Ad + (ldu + u) * 8);\
            CP16(da, Ab + (ldu + u) * 8);                                        \
            unsigned db = (unsigned)__cvta_generic_to_shared(Bd + (ldu + u) * 8);\
            CP16(db, Wb + (ldu + u) * 8);                                        \
        }                                                                        \
        asm volatile("cp.async.commit_group;");                                  \
    }

    LOAD_STAGE(0, 0);
    LOAD_STAGE(1, 1);

#pragma unroll
    for (int kc = 0; kc < NC; ++kc) {
        const int cur = kc % NSTAGE;
        if (kc + 2 < NC) {
            asm volatile("cp.async.wait_group 1;");
        } else {
            asm volatile("cp.async.wait_group 0;");
        }
        __syncthreads();
        if (kc + 2 < NC) LOAD_STAGE(kc + 2, (kc + 2) % NSTAGE);

        const __nv_bfloat16* Ad = As + cur * STAGE_ELEMS;
        const __nv_bfloat16* Bd = Bs + cur * STAGE_ELEMS;
#pragma unroll
        for (int ks = 0; ks < 4; ++ks) {
            const int kb = ks * 16;
            uint32_t a[4][4], b[2][4];
#pragma unroll
            for (int mt = 0; mt < 4; ++mt) {
                unsigned ad = (unsigned)__cvta_generic_to_shared(
                    Ad + (a_row + mt * 16) * PITCH + kb + a_col);
                LDSM4(a[mt][0], a[mt][1], a[mt][2], a[mt][3], ad);
            }
#pragma unroll
            for (int p = 0; p < 2; ++p) {
                unsigned bd = (unsigned)__cvta_generic_to_shared(
                    Bd + (b_row + p * 16) * PITCH + kb + b_col);
                LDSM4(b[p][0], b[p][1], b[p][2], b[p][3], bd);
            }
#pragma unroll
            for (int mt = 0; mt < 4; ++mt)
#pragma unroll
                for (int nt = 0; nt < 4; ++nt)
                    MMA_BF16(acc[mt][nt], a[mt], b[nt >> 1][(nt & 1) * 2],
                             b[nt >> 1][(nt & 1) * 2 + 1]);
        }
        __syncthreads();
    }

#pragma unroll
    for (int mt = 0; mt < 4; ++mt) {
#pragma unroll
        for (int nt = 0; nt < 4; ++nt) {
            size_t row = row0 + wm + mt * 16 + g;
            int col = col0 + wn + nt * 8 + 2 * tg;
            float b0 = BIAS ? bvec[col] : 0.f, b1 = BIAS ? bvec[col + 1] : 0.f;
            *(float2*)&C[row * NTOT + col] =
                make_float2(acc[mt][nt][0] + b0, acc[mt][nt][1] + b1);
            *(float2*)&C[(row + 8) * NTOT + col] =
                make_float2(acc[mt][nt][2] + b0, acc[mt][nt][3] + b1);
        }
    }
}

// ---------------- tensor-core attention (register-resident P, fp16 PV) ------
// blockIdx.y < 8: self head y; >= 8: mutual head y-8.
// 4 warps x 32 query rows. Q: A-side split K'=48 (x0.25); K: B-side split.
// V: plain fp16, Vt[d][m] (pitch 136). P stays in registers as fp16 A-frags.
#define PQ 56
#define PVH 136
#define ATTN_SMEM ((2 * 128 * PQ + 16 * PVH) * 2)

__global__ void __launch_bounds__(128) attn_tc(const float* __restrict__ mask)
{
    extern __shared__ __nv_bfloat16 sm[];
    __nv_bfloat16* Qs = sm;
    __nv_bfloat16* Ks = sm + 128 * PQ;
    ush* VtH = (ush*)(sm + 2 * 128 * PQ);

    const int b = blockIdx.x;
    const bool self = blockIdx.y < 8;
    const int h = self ? blockIdx.y : blockIdx.y - 8;
    const int tid = threadIdx.x, lane = tid & 31, wid = tid >> 5;
    const float* base = (self ? g_qkv_self : g_qkv_mut) + (size_t)b * NTOK * 384;

    // ---- convert Q, K, V into smem ----
    {
        int qrow = self ? tid : ((tid < 64) ? 64 + tid : tid - 64);
        const float* qp = base + qrow * 384 + h * HD;
        ush buf[48];
#pragma unroll
        for (int j = 0; j < 16; ++j) {
            ush hh, ll;
            split_hl(qp[j] * 0.25f, hh, ll);
            buf[3 * j] = hh; buf[3 * j + 1] = hh; buf[3 * j + 2] = ll;
        }
        uint4* qd = (uint4*)(Qs + tid * PQ);
        const uint4* s = (const uint4*)buf;
#pragma unroll
        for (int u = 0; u < 6; ++u) qd[u] = s[u];

        const float* kp = base + tid * 384 + 128 + h * HD;
#pragma unroll
        for (int j = 0; j < 16; ++j) {
            ush hh, ll;
            split_hl(kp[j], hh, ll);
            buf[3 * j] = hh; buf[3 * j + 1] = ll; buf[3 * j + 2] = hh;
        }
        uint4* kd = (uint4*)(Ks + tid * PQ);
#pragma unroll
        for (int u = 0; u < 6; ++u) kd[u] = s[u];

        const float* vp = base + tid * 384 + 256 + h * HD;
#pragma unroll
        for (int d = 0; d < 16; ++d) {
            __half hv = __float2half_rn(vp[d]);
            VtH[d * PVH + tid] = *(ush*)&hv;
        }
    }
    __syncthreads();

    const int g = lane >> 2, tg = lane & 3;
    const int r0 = wid * 32;
    const int a_row = lane & 15, a_col = (lane >> 4) * 8;
    const int bq = lane >> 3;
    const int b_rsub = ((bq >> 1) * 8) + (lane & 7);
    const int b_col8 = (bq & 1) * 8;

    const int nchunk = self ? 4 : 2;
    const int kb0 = (self || wid < 2) ? 0 : 64;
    const float* mbA_base = self
        ? g_mbias + ((size_t)h * 512 + (b & 511)) * 16384
        : mask + (size_t)(b & 511) * 16384;

    float accO[2][2][4] = {};
    float rs[4] = {0.f, 0.f, 0.f, 0.f};

    for (int mc = 0; mc < nchunk; ++mc) {
        const int key0 = kb0 + mc * 32;
        // ---- scores: S[32, 32] = Qs[r0..][48] @ Ks[key0..][48]^T ----
        float accS[2][4][4] = {};
#pragma unroll
        for (int kt = 0; kt < 3; ++kt) {
            uint32_t a[2][4], bf[2][4];
#pragma unroll
            for (int mt = 0; mt < 2; ++mt) {
                unsigned ad = (unsigned)__cvta_generic_to_shared(
                    Qs + (r0 + mt * 16 + a_row) * PQ + kt * 16 + a_col);
                LDSM4(a[mt][0], a[mt][1], a[mt][2], a[mt][3], ad);
            }
#pragma unroll
            for (int p = 0; p < 2; ++p) {
                unsigned bd = (unsigned)__cvta_generic_to_shared(
                    Ks + (key0 + p * 16 + b_rsub) * PQ + kt * 16 + b_col8);
                LDSM4(bf[p][0], bf[p][1], bf[p][2], bf[p][3], bd);
            }
#pragma unroll
            for (int mt = 0; mt < 2; ++mt)
#pragma unroll
                for (int nt = 0; nt < 4; ++nt)
                    MMA_BF16(accS[mt][nt], a[mt], bf[nt >> 1][(nt & 1) * 2],
                             bf[nt >> 1][(nt & 1) * 2 + 1]);
        }
        // ---- bias + exp in place + row-sum partials ----
#pragma unroll
        for (int mt = 0; mt < 2; ++mt) {
            const int rA = r0 + mt * 16 + g;
            const float* mrA = mbA_base + (self ? rA : (rA & 63)) * 128;
            const float* mrB = mbA_base + (self ? (rA + 8) : ((rA + 8) & 63)) * 128;
#pragma unroll
            for (int nt = 0; nt < 4; ++nt) {
                const int ml = (self ? key0 : mc * 32) + nt * 8 + 2 * tg;
                float2 mA = *(const float2*)(mrA + ml);
                float2 mB = *(const float2*)(mrB + ml);
                float p0 = __expf(accS[mt][nt][0] + mA.x);
                float p1 = __expf(accS[mt][nt][1] + mA.y);
                float p2 = __expf(accS[mt][nt][2] + mB.x);
                float p3 = __expf(accS[mt][nt][3] + mB.y);
                rs[2 * mt]     += p0 + p1;
                rs[2 * mt + 1] += p2 + p3;
                accS[mt][nt][0] = p0; accS[mt][nt][1] = p1;
                accS[mt][nt][2] = p2; accS[mt][nt][3] = p3;
            }
        }
        // ---- PV: O[32,16] += P(frag,fp16) @ Vt[16, key0..key0+31]^T ----
#pragma unroll
        for (int kt2 = 0; kt2 < 2; ++kt2) {
            uint32_t a2[2][4];
#pragma unroll
            for (int mt = 0; mt < 2; ++mt) {
                CVT_F16X2(a2[mt][0], accS[mt][2 * kt2][1],     accS[mt][2 * kt2][0]);
                CVT_F16X2(a2[mt][1], accS[mt][2 * kt2][3],     accS[mt][2 * kt2][2]);
                CVT_F16X2(a2[mt][2], accS[mt][2 * kt2 + 1][1], accS[mt][2 * kt2 + 1][0]);
                CVT_F16X2(a2[mt][3], accS[mt][2 * kt2 + 1][3], accS[mt][2 * kt2 + 1][2]);
            }
            uint32_t b2[4];
            unsigned bd = (unsigned)__cvta_generic_to_shared(
                VtH + b_rsub * PVH + key0 + kt2 * 16 + b_col8);
            LDSM4(b2[0], b2[1], b2[2], b2[3], bd);
#pragma unroll
            for (int mt = 0; mt < 2; ++mt) {
                MMA_F16(accO[mt][0], a2[mt], b2[0], b2[1]);
                MMA_F16(accO[mt][1], a2[mt], b2[2], b2[3]);
            }
        }
    }

    // ---- row-sum reduce over the tg quad ----
#pragma unroll
    for (int s = 0; s < 4; ++s) {
        rs[s] += __shfl_xor_sync(0xffffffffu, rs[s], 1);
        rs[s] += __shfl_xor_sync(0xffffffffu, rs[s], 2);
    }
    float inv[4];
#pragma unroll
    for (int s = 0; s < 4; ++s) inv[s] = 1.f / rs[s];

    // ---- write O (split triplets) to g_concat3 ----
    const int cbase = self ? 384 : 0;    // (128 cols) * 3 for self half
#pragma unroll
    for (int mt = 0; mt < 2; ++mt) {
#pragma unroll
        for (int nt2 = 0; nt2 < 2; ++nt2) {
            const int d0 = nt2 * 8 + 2 * tg;
            const int rA = r0 + mt * 16 + g;
            unsigned tb[3];
            trip2(accO[mt][nt2][0] * inv[2 * mt], accO[mt][nt2][1] * inv[2 * mt], tb);
            unsigned* oA = (unsigned*)(g_concat3 +
                ((size_t)b * NTOK + rA) * 768 + cbase + (h * HD + d0) * 3);
            oA[0] = tb[0]; oA[1] = tb[1]; oA[2] = tb[2];
            trip2(accO[mt][nt2][2] * inv[2 * mt + 1], accO[mt][nt2][3] * inv[2 * mt + 1], tb);
            unsigned* oB = (unsigned*)(g_concat3 +
                ((size_t)b * NTOK + rA + 8) * 768 + cbase + (h * HD + d0) * 3);
            oB[0] = tb[0]; oB[1] = tb[1]; oB[2] = tb[2];
        }
    }
}

// ---------------- launch ----------------------------------------------------
extern "C" void kernel_launch(void* const* d_in, const int* in_sizes, int n_in,
                              void* d_out, int out_size)
{
    const float* x         = (const float*)d_in[0];
    const float* mask      = (const float*)d_in[1];
    const float* w_self    = (const float*)d_in[2];
    const float* w_mut     = (const float*)d_in[3];
    const float* w_proj    = (const float*)d_in[4];
    const float* b_proj    = (const float*)d_in[5];
    const float* rpe_table = (const float*)d_in[6];
    const float* pe        = (const float*)d_in[7];
    const int*   rpe_index = (const int*)d_in[8];
    float* out = (float*)d_out;

    ush *xs, *xpes, *cc, *ws, *wm, *wp;
    float *qs, *qm;
    cudaGetSymbolAddress((void**)&ws, g_ws3);
    cudaGetSymbolAddress((void**)&wm, g_wm3);
    cudaGetSymbolAddress((void**)&wp, g_wp3);
    cudaGetSymbolAddress((void**)&xs, g_xs3);
    cudaGetSymbolAddress((void**)&xpes, g_xpes3);
    cudaGetSymbolAddress((void**)&qs, g_qkv_self);
    cudaGetSymbolAddress((void**)&qm, g_qkv_mut);
    cudaGetSymbolAddress((void**)&cc, g_concat3);

    const int SMEM = 2 * NSTAGE * STAGE_ELEMS * (int)sizeof(__nv_bfloat16); // 110592
    cudaFuncSetAttribute(gemm_bf16<384, 384, false>,
                         cudaFuncAttributeMaxDynamicSharedMemorySize, SMEM);
    cudaFuncSetAttribute(gemm_bf16<768, 128, true>,
                         cudaFuncAttributeMaxDynamicSharedMemorySize, SMEM);
    cudaFuncSetAttribute(attn_tc,
                         cudaFuncAttributeMaxDynamicSharedMemorySize, ATTN_SMEM);

    // launch 1: all prep (weights, x-split, fused mbias)
    prep_all<<<16896, 256>>>(x, pe, w_self, w_mut, w_proj, mask, rpe_index, rpe_table);

    // launches 2,3: QKV GEMMs (K' = 384)
    gemm_bf16<384, 384, false><<<dim3(3, 1024), 256, SMEM>>>(
        (const __nv_bfloat16*)xs,   (const __nv_bfloat16*)ws, nullptr, qs);
    gemm_bf16<384, 384, false><<<dim3(3, 1024), 256, SMEM>>>(
        (const __nv_bfloat16*)xpes, (const __nv_bfloat16*)wm, nullptr, qm);

    // launch 4: tensor-core attention  (<- ncu capture slot)
    attn_tc<<<dim3(WB, 16), 128, ATTN_SMEM>>>(mask);

    // launch 5: projection (K' = 768)
    gemm_bf16<768, 128, true><<<dim3(1, 1024), 256, SMEM>>>(
        (const __nv_bfloat16*)cc, (const __nv_bfloat16*)wp, b_proj, out);
}

// round 12
// speedup vs baseline: 1.2104x; 1.1107x over previous
#include <cuda_runtime.h>
#include <cuda_bf16.h>
#include <cstddef>
#include <cstdint>

#define WB     1024
#define NTOK   128
#define NHEADS 8
#define HD     16
#define MROWS  (WB * NTOK)          // 131072

typedef unsigned long long ull;
typedef unsigned short ush;

// ---------------- scratch (device globals; no runtime allocation) ----------
__device__ ush g_xs3  [(size_t)MROWS * 384];
__device__ ush g_xpes3[(size_t)MROWS * 384];
__device__ ush g_ws3  [384 * 384];
__device__ ush g_wm3  [384 * 384];
__device__ ush g_wp3  [128 * 768];
__device__ float g_qkv_self[(size_t)MROWS * 384];
__device__ float g_qkv_mut [(size_t)MROWS * 384];
__device__ ush g_concat3[(size_t)MROWS * 768];
// fragment-ordered bias tables
__device__ float g_mbf [(size_t)NHEADS * 512 * 16 * 1024]; // [h][w][qt*4+kt][1024]
__device__ float g_mmf [(size_t)512 * 4 * 1024];           // [w][qt2*2+kt2][1024]

__device__ __forceinline__ void split_hl(float v, ush& h, ush& l) {
    __nv_bfloat16 hh = __float2bfloat16(v);
    float r = v - __bfloat162float(hh);
    __nv_bfloat16 ll = __float2bfloat16(r);
    h = *(ush*)&hh;
    l = *(ush*)&ll;
}

__device__ __forceinline__ void trip2(float a, float b, unsigned* o) {
    ush h0, l0, h1, l1;
    split_hl(a, h0, l0); split_hl(b, h1, l1);
    o[0] = (unsigned)h0 | ((unsigned)h0 << 16);
    o[1] = (unsigned)l0 | ((unsigned)h1 << 16);
    o[2] = (unsigned)h1 | ((unsigned)l1 << 16);
}

// ---------------- fused prep (ONE launch) -----------------------------------
// [0,512):       weight split (B-side h,l,h)
// [512,8704):    x split (A-side h,h,l) + x+pe split
// [8704,16896):  fragment-ordered self bias  g_mbf
// [16896,17408): fragment-ordered mutual mask g_mmf
__global__ void __launch_bounds__(256) prep_all(
    const float* __restrict__ x, const float* __restrict__ pe,
    const float* __restrict__ ws, const float* __restrict__ wm,
    const float* __restrict__ wp, const float* __restrict__ mask,
    const int* __restrict__ rpe_index, const float* __restrict__ rpe_table)
{
    const int bid = blockIdx.x, tid = threadIdx.x;
    if (bid < 512) {
        int i = bid * 256 + tid;
        float v; ush* dst;
        if (i < 49152)       { v = ws[i];          dst = g_ws3 + 3 * i; }
        else if (i < 98304)  { v = wm[i - 49152];  dst = g_wm3 + 3 * (i - 49152); }
        else                 { v = wp[i - 98304];  dst = g_wp3 + 3 * (i - 98304); }
        ush h, l;
        split_hl(v, h, l);
        dst[0] = h; dst[1] = l; dst[2] = h;
        return;
    }
    if (bid < 8704) {
        size_t idx8 = (size_t)(bid - 512) * 256 + tid;
        size_t e0 = idx8 * 8;
        int c = (int)(e0 & 127);
        int t = (int)((e0 >> 7) & 127);
        float4 xv0 = ((const float4*)x)[idx8 * 2];
        float4 xv1 = ((const float4*)x)[idx8 * 2 + 1];
        const float* pp = pe + (t & 63) * 128 + c;
        float xe[8] = {xv0.x, xv0.y, xv0.z, xv0.w, xv1.x, xv1.y, xv1.z, xv1.w};
        ush b0[24], b1[24];
#pragma unroll
        for (int j = 0; j < 8; ++j) {
            ush h, l;
            split_hl(xe[j], h, l);
            b0[3 * j] = h; b0[3 * j + 1] = h; b0[3 * j + 2] = l;
            split_hl(xe[j] + pp[j], h, l);
            b1[3 * j] = h; b1[3 * j + 1] = h; b1[3 * j + 2] = l;
        }
        uint4* d0 = (uint4*)(g_xs3 + 3 * e0);
        uint4* d1 = (uint4*)(g_xpes3 + 3 * e0);
        const uint4* s0 = (const uint4*)b0;
        const uint4* s1 = (const uint4*)b1;
        d0[0] = s0[0]; d0[1] = s0[1]; d0[2] = s0[2];
        d1[0] = s1[0]; d1[1] = s1[1]; d1[2] = s1[2];
        return;
    }
    const int q = tid >> 5, lane = tid & 31, g = lane >> 2, tg = lane & 3;
    const int il = (q >> 2) * 16 + ((q >> 1) & 1) * 8 + g;   // row within 32-tile
    const int ml0 = (q & 1) * 16 + 2 * tg;                   // col e0 within 32-tile
    if (bid < 16896) {
        int blin = bid - 8704;                   // 0..8191
        int w = blin >> 4, tile = blin & 15;
        int qt = tile >> 2, kt = tile & 3;
        int i = qt * 32 + il;
        int m0 = kt * 32 + ml0;
        const float* mrow = mask + (size_t)w * 16384 + i * 128;
        float2 mv01 = *(const float2*)(mrow + m0);
        float2 mv23 = *(const float2*)(mrow + m0 + 8);
        const int* irow = rpe_index + i * 128;
        int2 ix01 = *(const int2*)(irow + m0);
        int2 ix23 = *(const int2*)(irow + m0 + 8);
        float t0[8], t1[8], t2[8], t3[8];
        *(float4*)t0 = *(const float4*)(rpe_table + ix01.x * 8);
        *(float4*)(t0+4) = *(const float4*)(rpe_table + ix01.x * 8 + 4);
        *(float4*)t1 = *(const float4*)(rpe_table + ix01.y * 8);
        *(float4*)(t1+4) = *(const float4*)(rpe_table + ix01.y * 8 + 4);
        *(float4*)t2 = *(const float4*)(rpe_table + ix23.x * 8);
        *(float4*)(t2+4) = *(const float4*)(rpe_table + ix23.x * 8 + 4);
        *(float4*)t3 = *(const float4*)(rpe_table + ix23.y * 8);
        *(float4*)(t3+4) = *(const float4*)(rpe_table + ix23.y * 8 + 4);
#pragma unroll
        for (int h = 0; h < NHEADS; ++h) {
            float4 o = make_float4(mv01.x + t0[h], mv01.y + t1[h],
                                   mv23.x + t2[h], mv23.y + t3[h]);
            *(float4*)(g_mbf + (((size_t)h * 512 + w) * 16 + tile) * 1024 + tid * 4) = o;
        }
        return;
    }
    {
        int w = bid - 16896;                     // 0..511
        const float* mb = mask + (size_t)w * 16384;
#pragma unroll
        for (int tile = 0; tile < 4; ++tile) {
            int qt2 = tile >> 1, kt2 = tile & 1;
            int i = qt2 * 32 + il;
            int m0 = kt2 * 32 + ml0;
            float2 mv01 = *(const float2*)(mb + i * 128 + m0);
            float2 mv23 = *(const float2*)(mb + i * 128 + m0 + 8);
            *(float4*)(g_mmf + ((size_t)w * 4 + tile) * 1024 + tid * 4) =
                make_float4(mv01.x, mv01.y, mv23.x, mv23.y);
        }
    }
}

// ---------------- mma / ldsm / cp.async macros ------------------------------
#define MMA_BF16(d, a, b0r, b1r) \
    asm volatile("mma.sync.aligned.m16n8k16.row.col.f32.bf16.bf16.f32 " \
        "{%0,%1,%2,%3},{%4,%5,%6,%7},{%8,%9},{%0,%1,%2,%3};" \
        : "+f"(d[0]), "+f"(d[1]), "+f"(d[2]), "+f"(d[3]) \
        : "r"(a[0]), "r"(a[1]), "r"(a[2]), "r"(a[3]), "r"(b0r), "r"(b1r))

#define MMA_F16(d, a, b0r, b1r) \
    asm volatile("mma.sync.aligned.m16n8k16.row.col.f32.f16.f16.f32 " \
        "{%0,%1,%2,%3},{%4,%5,%6,%7},{%8,%9},{%0,%1,%2,%3};" \
        : "+f"(d[0]), "+f"(d[1]), "+f"(d[2]), "+f"(d[3]) \
        : "r"(a[0]), "r"(a[1]), "r"(a[2]), "r"(a[3]), "r"(b0r), "r"(b1r))

#define LDSM4(r0, r1, r2, r3, addr) \
    asm volatile("ldmatrix.sync.aligned.m8n8.x4.shared.b16 {%0,%1,%2,%3}, [%4];" \
        : "=r"(r0), "=r"(r1), "=r"(r2), "=r"(r3) : "r"(addr))

#define CP16(dst, src) \
    asm volatile("cp.async.cg.shared.global [%0], [%1], 16;" :: "r"(dst), "l"(src))

#define CVT_F16X2(d, hi, lo) \
    asm("cvt.rn.f16x2.f32 %0, %1, %2;" : "=r"(d) : "f"(hi), "f"(lo))

#define PITCH 72
#define STAGE_ELEMS (128 * PITCH)
#define NSTAGE 3

template<int KTOT, int NTOT, bool BIAS>
__global__ void __launch_bounds__(256) gemm_bf16(
    const __nv_bfloat16* __restrict__ A, const __nv_bfloat16* __restrict__ W,
    const float* __restrict__ bvec, float* __restrict__ C)
{
    extern __shared__ __nv_bfloat16 smem[];
    __nv_bfloat16* As = smem;
    __nv_bfloat16* Bs = smem + NSTAGE * STAGE_ELEMS;

    const int tid = threadIdx.x;
    const int lane = tid & 31, wid = tid >> 5;
    const int wm = (wid & 1) * 64, wn = (wid >> 1) * 32;
    const int g = lane >> 2, tg = lane & 3;
    const size_t row0 = (size_t)blockIdx.y * 128;
    const int col0 = blockIdx.x * 128;
    constexpr int NC = KTOT / 64;

    const int ldr = tid >> 1;
    const int ldu = (tid & 1) * 4;

    float acc[4][4][4] = {};

    const int a_row = wm + (lane & 15);
    const int a_col = (lane >> 4) * 8;
    const int bq = lane >> 3;
    const int b_row = wn + ((bq >> 1) * 8) + (lane & 7);
    const int b_col = (bq & 1) * 8;

#define LOAD_STAGE(kc, s)                                                        \
    {                                                                            \
        const __nv_bfloat16* Ab = A + (row0 + ldr) * KTOT + (kc) * 64;           \
        const __nv_bfloat16* Wb = W + (size_t)(col0 + ldr) * KTOT + (kc) * 64;   \
        __nv_bfloat16* Ad = As + (s) * STAGE_ELEMS + ldr * PITCH;                \
        __nv_bfloat16* Bd = Bs + (s) * STAGE_ELEMS + ldr * PITCH;                \
        _Pragma("unroll")                                                        \
        for (int u = 0; u < 4; ++u) {                                            \
            unsigned da = (unsigned)__cvta_generic_to_shared(Ad + (ldu + u) * 8);\
            CP16(da, Ab + (ldu + u) * 8);                                        \
            unsigned db = (unsigned)__cvta_generic_to_shared(Bd + (ldu + u) * 8);\
            CP16(db, Wb + (ldu + u) * 8);                                        \
        }                                                                        \
        asm volatile("cp.async.commit_group;");                                  \
    }

    LOAD_STAGE(0, 0);
    LOAD_STAGE(1, 1);

#pragma unroll
    for (int kc = 0; kc < NC; ++kc) {
        const int cur = kc % NSTAGE;
        if (kc + 2 < NC) {
            asm volatile("cp.async.wait_group 1;");
        } else {
            asm volatile("cp.async.wait_group 0;");
        }
        __syncthreads();
        if (kc + 2 < NC) LOAD_STAGE(kc + 2, (kc + 2) % NSTAGE);

        const __nv_bfloat16* Ad = As + cur * STAGE_ELEMS;
        const __nv_bfloat16* Bd = Bs + cur * STAGE_ELEMS;
#pragma unroll
        for (int ks = 0; ks < 4; ++ks) {
            const int kb = ks * 16;
            uint32_t a[4][4], b[2][4];
#pragma unroll
            for (int mt = 0; mt < 4; ++mt) {
                unsigned ad = (unsigned)__cvta_generic_to_shared(
                    Ad + (a_row + mt * 16) * PITCH + kb + a_col);
                LDSM4(a[mt][0], a[mt][1], a[mt][2], a[mt][3], ad);
            }
#pragma unroll
            for (int p = 0; p < 2; ++p) {
                unsigned bd = (unsigned)__cvta_generic_to_shared(
                    Bd + (b_row + p * 16) * PITCH + kb + b_col);
                LDSM4(b[p][0], b[p][1], b[p][2], b[p][3], bd);
            }
#pragma unroll
            for (int mt = 0; mt < 4; ++mt)
#pragma unroll
                for (int nt = 0; nt < 4; ++nt)
                    MMA_BF16(acc[mt][nt], a[mt], b[nt >> 1][(nt & 1) * 2],
                             b[nt >> 1][(nt & 1) * 2 + 1]);
        }
        __syncthreads();
    }

#pragma unroll
    for (int mt = 0; mt < 4; ++mt) {
#pragma unroll
        for (int nt = 0; nt < 4; ++nt) {
            size_t row = row0 + wm + mt * 16 + g;
            int col = col0 + wn + nt * 8 + 2 * tg;
            float b0 = BIAS ? bvec[col] : 0.f, b1 = BIAS ? bvec[col + 1] : 0.f;
            *(float2*)&C[row * NTOT + col] =
                make_float2(acc[mt][nt][0] + b0, acc[mt][nt][1] + b1);
            *(float2*)&C[(row + 8) * NTOT + col] =
                make_float2(acc[mt][nt][2] + b0, acc[mt][nt][3] + b1);
        }
    }
}

// ---------------- tensor-core attention --------------------------------------
// register-resident P (fp16), fragment-ordered bias tables, hoisted Q frags.
#define PQ 56
#define PVH 136
#define ATTN_SMEM ((2 * 128 * PQ + 16 * PVH) * 2)

__global__ void __launch_bounds__(128) attn_tc()
{
    extern __shared__ __nv_bfloat16 sm[];
    __nv_bfloat16* Qs = sm;
    __nv_bfloat16* Ks = sm + 128 * PQ;
    ush* VtH = (ush*)(sm + 2 * 128 * PQ);

    const int b = blockIdx.x;
    const bool self = blockIdx.y < 8;
    const int h = self ? blockIdx.y : blockIdx.y - 8;
    const int tid = threadIdx.x, lane = tid & 31, wid = tid >> 5;
    const float* base = (self ? g_qkv_self : g_qkv_mut) + (size_t)b * NTOK * 384;

    // ---- convert Q, K, V into smem ----
    {
        int qrow = self ? tid : ((tid < 64) ? 64 + tid : tid - 64);
        const float* qp = base + qrow * 384 + h * HD;
        ush buf[48];
#pragma unroll
        for (int j = 0; j < 16; ++j) {
            ush hh, ll;
            split_hl(qp[j] * 0.25f, hh, ll);
            buf[3 * j] = hh; buf[3 * j + 1] = hh; buf[3 * j + 2] = ll;
        }
        uint4* qd = (uint4*)(Qs + tid * PQ);
        const uint4* s = (const uint4*)buf;
#pragma unroll
        for (int u = 0; u < 6; ++u) qd[u] = s[u];

        const float* kp = base + tid * 384 + 128 + h * HD;
#pragma unroll
        for (int j = 0; j < 16; ++j) {
            ush hh, ll;
            split_hl(kp[j], hh, ll);
            buf[3 * j] = hh; buf[3 * j + 1] = ll; buf[3 * j + 2] = hh;
        }
        uint4* kd = (uint4*)(Ks + tid * PQ);
#pragma unroll
        for (int u = 0; u < 6; ++u) kd[u] = s[u];

        const float* vp = base + tid * 384 + 256 + h * HD;
#pragma unroll
        for (int d = 0; d < 16; ++d) {
            __half hv = __float2half_rn(vp[d]);
            VtH[d * PVH + tid] = *(ush*)&hv;
        }
    }
    __syncthreads();

    const int g = lane >> 2, tg = lane & 3;
    const int r0 = wid * 32;
    const int a_row = lane & 15, a_col = (lane >> 4) * 8;
    const int bq = lane >> 3;
    const int b_rsub = ((bq >> 1) * 8) + (lane & 7);
    const int b_col8 = (bq & 1) * 8;

    const int nchunk = self ? 4 : 2;
    const int kb0 = (self || wid < 2) ? 0 : 64;
    // fragment-ordered bias tile base (advance by 1024 per chunk)
    const float4* bias_t = self
        ? (const float4*)(g_mbf + (((size_t)h * 512 + (b & 511)) * 16 + wid * 4) * 1024)
        : (const float4*)(g_mmf + ((size_t)(b & 511) * 4 + (wid & 1) * 2) * 1024);

    // hoisted Q fragments
    uint32_t aq[3][2][4];
#pragma unroll
    for (int kt = 0; kt < 3; ++kt)
#pragma unroll
        for (int mt = 0; mt < 2; ++mt) {
            unsigned ad = (unsigned)__cvta_generic_to_shared(
                Qs + (r0 + mt * 16 + a_row) * PQ + kt * 16 + a_col);
            LDSM4(aq[kt][mt][0], aq[kt][mt][1], aq[kt][mt][2], aq[kt][mt][3], ad);
        }

    float accO[2][2][4] = {};
    float rs[4] = {0.f, 0.f, 0.f, 0.f};

    for (int mc = 0; mc < nchunk; ++mc) {
        const int key0 = kb0 + mc * 32;
        // issue bias loads early (consumed after the MMAs)
        float4 f[8];
        const float4* ft = bias_t + (size_t)mc * 256;   // 1024 floats = 256 float4
#pragma unroll
        for (int q = 0; q < 8; ++q) f[q] = ft[q * 32 + lane];

        // ---- scores ----
        float accS[2][4][4] = {};
#pragma unroll
        for (int kt = 0; kt < 3; ++kt) {
            uint32_t bf[2][4];
#pragma unroll
            for (int p = 0; p < 2; ++p) {
                unsigned bd = (unsigned)__cvta_generic_to_shared(
                    Ks + (key0 + p * 16 + b_rsub) * PQ + kt * 16 + b_col8);
                LDSM4(bf[p][0], bf[p][1], bf[p][2], bf[p][3], bd);
            }
#pragma unroll
            for (int mt = 0; mt < 2; ++mt)
#pragma unroll
                for (int nt = 0; nt < 4; ++nt)
                    MMA_BF16(accS[mt][nt], aq[kt][mt], bf[nt >> 1][(nt & 1) * 2],
                             bf[nt >> 1][(nt & 1) * 2 + 1]);
        }
        // ---- bias + exp + row-sum partials ----
#pragma unroll
        for (int mt = 0; mt < 2; ++mt) {
#pragma unroll
            for (int nt = 0; nt < 4; ++nt) {
                const float* f0 = (const float*)&f[mt * 4 + (nt >> 1)];
                const float* f1 = (const float*)&f[mt * 4 + 2 + (nt >> 1)];
                const int e0 = (nt & 1) * 2;
                float p0 = __expf(accS[mt][nt][0] + f0[e0]);
                float p1 = __expf(accS[mt][nt][1] + f0[e0 + 1]);
                float p2 = __expf(accS[mt][nt][2] + f1[e0]);
                float p3 = __expf(accS[mt][nt][3] + f1[e0 + 1]);
                rs[2 * mt]     += p0 + p1;
                rs[2 * mt + 1] += p2 + p3;
                accS[mt][nt][0] = p0; accS[mt][nt][1] = p1;
                accS[mt][nt][2] = p2; accS[mt][nt][3] = p3;
            }
        }
        // ---- PV (fp16) ----
#pragma unroll
        for (int kt2 = 0; kt2 < 2; ++kt2) {
            uint32_t a2[2][4];
#pragma unroll
            for (int mt = 0; mt < 2; ++mt) {
                CVT_F16X2(a2[mt][0], accS[mt][2 * kt2][1],     accS[mt][2 * kt2][0]);
                CVT_F16X2(a2[mt][1], accS[mt][2 * kt2][3],     accS[mt][2 * kt2][2]);
                CVT_F16X2(a2[mt][2], accS[mt][2 * kt2 + 1][1], accS[mt][2 * kt2 + 1][0]);
                CVT_F16X2(a2[mt][3], accS[mt][2 * kt2 + 1][3], accS[mt][2 * kt2 + 1][2]);
            }
            uint32_t b2[4];
            unsigned bd = (unsigned)__cvta_generic_to_shared(
                VtH + b_rsub * PVH + key0 + kt2 * 16 + b_col8);
            LDSM4(b2[0], b2[1], b2[2], b2[3], bd);
#pragma unroll
            for (int mt = 0; mt < 2; ++mt) {
                MMA_F16(accO[mt][0], a2[mt], b2[0], b2[1]);
                MMA_F16(accO[mt][1], a2[mt], b2[2], b2[3]);
            }
        }
    }

    // ---- row-sum reduce over the tg quad ----
#pragma unroll
    for (int s = 0; s < 4; ++s) {
        rs[s] += __shfl_xor_sync(0xffffffffu, rs[s], 1);
        rs[s] += __shfl_xor_sync(0xffffffffu, rs[s], 2);
    }
    float inv[4];
#pragma unroll
    for (int s = 0; s < 4; ++s) inv[s] = 1.f / rs[s];

    // ---- write O (split triplets) to g_concat3 ----
    const int cbase = self ? 384 : 0;
#pragma unroll
    for (int mt = 0; mt < 2; ++mt) {
#pragma unroll
        for (int nt2 = 0; nt2 < 2; ++nt2) {
            const int d0 = nt2 * 8 + 2 * tg;
            const int rA = r0 + mt * 16 + g;
            unsigned tb[3];
            trip2(accO[mt][nt2][0] * inv[2 * mt], accO[mt][nt2][1] * inv[2 * mt], tb);
            unsigned* oA = (unsigned*)(g_concat3 +
                ((size_t)b * NTOK + rA) * 768 + cbase + (h * HD + d0) * 3);
            oA[0] = tb[0]; oA[1] = tb[1]; oA[2] = tb[2];
            trip2(accO[mt][nt2][2] * inv[2 * mt + 1], accO[mt][nt2][3] * inv[2 * mt + 1], tb);
            unsigned* oB = (unsigned*)(g_concat3 +
                ((size_t)b * NTOK + rA + 8) * 768 + cbase + (h * HD + d0) * 3);
            oB[0] = tb[0]; oB[1] = tb[1]; oB[2] = tb[2];
        }
    }
}

// ---------------- launch ----------------------------------------------------
extern "C" void kernel_launch(void* const* d_in, const int* in_sizes, int n_in,
                              void* d_out, int out_size)
{
    const float* x         = (const float*)d_in[0];
    const float* mask      = (const float*)d_in[1];
    const float* w_self    = (const float*)d_in[2];
    const float* w_mut     = (const float*)d_in[3];
    const float* w_proj    = (const float*)d_in[4];
    const float* b_proj    = (const float*)d_in[5];
    const float* rpe_table = (const float*)d_in[6];
    const float* pe        = (const float*)d_in[7];
    const int*   rpe_index = (const int*)d_in[8];
    float* out = (float*)d_out;

    ush *xs, *xpes, *cc, *ws, *wm, *wp;
    float *qs, *qm;
    cudaGetSymbolAddress((void**)&ws, g_ws3);
    cudaGetSymbolAddress((void**)&wm, g_wm3);
    cudaGetSymbolAddress((void**)&wp, g_wp3);
    cudaGetSymbolAddress((void**)&xs, g_xs3);
    cudaGetSymbolAddress((void**)&xpes, g_xpes3);
    cudaGetSymbolAddress((void**)&qs, g_qkv_self);
    cudaGetSymbolAddress((void**)&qm, g_qkv_mut);
    cudaGetSymbolAddress((void**)&cc, g_concat3);

    const int SMEM = 2 * NSTAGE * STAGE_ELEMS * (int)sizeof(__nv_bfloat16); // 110592
    cudaFuncSetAttribute(gemm_bf16<384, 384, false>,
                         cudaFuncAttributeMaxDynamicSharedMemorySize, SMEM);
    cudaFuncSetAttribute(gemm_bf16<768, 128, true>,
                         cudaFuncAttributeMaxDynamicSharedMemorySize, SMEM);
    cudaFuncSetAttribute(attn_tc,
                         cudaFuncAttributeMaxDynamicSharedMemorySize, ATTN_SMEM);

    // launch 1: all prep
    prep_all<<<17408, 256>>>(x, pe, w_self, w_mut, w_proj, mask, rpe_index, rpe_table);

    // launches 2,3: QKV GEMMs (K' = 384)
    gemm_bf16<384, 384, false><<<dim3(3, 1024), 256, SMEM>>>(
        (const __nv_bfloat16*)xs,   (const __nv_bfloat16*)ws, nullptr, qs);
    gemm_bf16<384, 384, false><<<dim3(3, 1024), 256, SMEM>>>(
        (const __nv_bfloat16*)xpes, (const __nv_bfloat16*)wm, nullptr, qm);

    // launch 4: tensor-core attention  (<- ncu capture slot)
    attn_tc<<<dim3(WB, 16), 128, ATTN_SMEM>>>();

    // launch 5: projection (K' = 768)
    gemm_bf16<768, 128, true><<<dim3(1, 1024), 256, SMEM>>>(
        (const __nv_bfloat16*)cc, (const __nv_bfloat16*)wp, b_proj, out);
}

// round 13
// speedup vs baseline: 1.5043x; 1.2428x over previous
#include <cuda_runtime.h>
#include <cuda_bf16.h>
#include <cuda_fp16.h>
#include <cstddef>
#include <cstdint>

#define WB     1024
#define NTOK   128
#define NHEADS 8
#define HD     16
#define MROWS  (WB * NTOK)          // 131072

typedef unsigned long long ull;
typedef unsigned short ush;

// ---------------- scratch (device globals; no runtime allocation) ----------
__device__ ush g_xs3  [(size_t)MROWS * 384];
__device__ ush g_xpes3[(size_t)MROWS * 384];
__device__ ush g_ws3  [384 * 384];
__device__ ush g_wm3  [384 * 384];
__device__ ush g_wp3  [128 * 768];
// attention-ready operands, written by QKV GEMM epilogue
__device__ ush g_q3s[(size_t)WB * NHEADS * NTOK * 48];  // A-side triplets (x0.25)
__device__ ush g_k3s[(size_t)WB * NHEADS * NTOK * 48];  // B-side triplets
__device__ ush g_vts[(size_t)WB * NHEADS * HD * NTOK];  // fp16, [bh][d][m]
__device__ ush g_q3m[(size_t)WB * NHEADS * NTOK * 48];
__device__ ush g_k3m[(size_t)WB * NHEADS * NTOK * 48];
__device__ ush g_vtm[(size_t)WB * NHEADS * HD * NTOK];
__device__ ush g_concat3[(size_t)MROWS * 768];
// fragment-ordered bias tables
__device__ float g_mbf [(size_t)NHEADS * 512 * 16 * 1024]; // [h][w][qt*4+kt][1024]
__device__ float g_mmf [(size_t)512 * 4 * 1024];           // [w][qt2*2+kt2][1024]

__device__ __forceinline__ void split_hl(float v, ush& h, ush& l) {
    __nv_bfloat16 hh = __float2bfloat16(v);
    float r = v - __bfloat162float(hh);
    __nv_bfloat16 ll = __float2bfloat16(r);
    h = *(ush*)&hh;
    l = *(ush*)&ll;
}

// A-side pair (h,h,l)(h,h,l)
__device__ __forceinline__ void trip2(float a, float b, unsigned* o) {
    ush h0, l0, h1, l1;
    split_hl(a, h0, l0); split_hl(b, h1, l1);
    o[0] = (unsigned)h0 | ((unsigned)h0 << 16);
    o[1] = (unsigned)l0 | ((unsigned)h1 << 16);
    o[2] = (unsigned)h1 | ((unsigned)l1 << 16);
}
// B-side pair (h,l,h)(h,l,h)
__device__ __forceinline__ void trip2B(float a, float b, unsigned* o) {
    ush h0, l0, h1, l1;
    split_hl(a, h0, l0); split_hl(b, h1, l1);
    o[0] = (unsigned)h0 | ((unsigned)l0 << 16);
    o[1] = (unsigned)h0 | ((unsigned)h1 << 16);
    o[2] = (unsigned)l1 | ((unsigned)h1 << 16);
}

// ---------------- fused prep (ONE launch) -----------------------------------
__global__ void __launch_bounds__(256) prep_all(
    const float* __restrict__ x, const float* __restrict__ pe,
    const float* __restrict__ ws, const float* __restrict__ wm,
    const float* __restrict__ wp, const float* __restrict__ mask,
    const int* __restrict__ rpe_index, const float* __restrict__ rpe_table)
{
    const int bid = blockIdx.x, tid = threadIdx.x;
    if (bid < 512) {
        int i = bid * 256 + tid;
        float v; ush* dst;
        if (i < 49152)       { v = ws[i];          dst = g_ws3 + 3 * i; }
        else if (i < 98304)  { v = wm[i - 49152];  dst = g_wm3 + 3 * (i - 49152); }
        else                 { v = wp[i - 98304];  dst = g_wp3 + 3 * (i - 98304); }
        ush h, l;
        split_hl(v, h, l);
        dst[0] = h; dst[1] = l; dst[2] = h;
        return;
    }
    if (bid < 8704) {
        size_t idx8 = (size_t)(bid - 512) * 256 + tid;
        size_t e0 = idx8 * 8;
        int c = (int)(e0 & 127);
        int t = (int)((e0 >> 7) & 127);
        float4 xv0 = ((const float4*)x)[idx8 * 2];
        float4 xv1 = ((const float4*)x)[idx8 * 2 + 1];
        const float* pp = pe + (t & 63) * 128 + c;
        float xe[8] = {xv0.x, xv0.y, xv0.z, xv0.w, xv1.x, xv1.y, xv1.z, xv1.w};
        ush b0[24], b1[24];
#pragma unroll
        for (int j = 0; j < 8; ++j) {
            ush h, l;
            split_hl(xe[j], h, l);
            b0[3 * j] = h; b0[3 * j + 1] = h; b0[3 * j + 2] = l;
            split_hl(xe[j] + pp[j], h, l);
            b1[3 * j] = h; b1[3 * j + 1] = h; b1[3 * j + 2] = l;
        }
        uint4* d0 = (uint4*)(g_xs3 + 3 * e0);
        uint4* d1 = (uint4*)(g_xpes3 + 3 * e0);
        const uint4* s0 = (const uint4*)b0;
        const uint4* s1 = (const uint4*)b1;
        d0[0] = s0[0]; d0[1] = s0[1]; d0[2] = s0[2];
        d1[0] = s1[0]; d1[1] = s1[1]; d1[2] = s1[2];
        return;
    }
    const int q = tid >> 5, lane = tid & 31, g = lane >> 2, tg = lane & 3;
    const int il = (q >> 2) * 16 + ((q >> 1) & 1) * 8 + g;
    const int ml0 = (q & 1) * 16 + 2 * tg;
    if (bid < 16896) {
        int blin = bid - 8704;
        int w = blin >> 4, tile = blin & 15;
        int qt = tile >> 2, kt = tile & 3;
        int i = qt * 32 + il;
        int m0 = kt * 32 + ml0;
        const float* mrow = mask + (size_t)w * 16384 + i * 128;
        float2 mv01 = *(const float2*)(mrow + m0);
        float2 mv23 = *(const float2*)(mrow + m0 + 8);
        const int* irow = rpe_index + i * 128;
        int2 ix01 = *(const int2*)(irow + m0);
        int2 ix23 = *(const int2*)(irow + m0 + 8);
        float t0[8], t1[8], t2[8], t3[8];
        *(float4*)t0 = *(const float4*)(rpe_table + ix01.x * 8);
        *(float4*)(t0+4) = *(const float4*)(rpe_table + ix01.x * 8 + 4);
        *(float4*)t1 = *(const float4*)(rpe_table + ix01.y * 8);
        *(float4*)(t1+4) = *(const float4*)(rpe_table + ix01.y * 8 + 4);
        *(float4*)t2 = *(const float4*)(rpe_table + ix23.x * 8);
        *(float4*)(t2+4) = *(const float4*)(rpe_table + ix23.x * 8 + 4);
        *(float4*)t3 = *(const float4*)(rpe_table + ix23.y * 8);
        *(float4*)(t3+4) = *(const float4*)(rpe_table + ix23.y * 8 + 4);
#pragma unroll
        for (int h = 0; h < NHEADS; ++h) {
            float4 o = make_float4(mv01.x + t0[h], mv01.y + t1[h],
                                   mv23.x + t2[h], mv23.y + t3[h]);
            *(float4*)(g_mbf + (((size_t)h * 512 + w) * 16 + tile) * 1024 + tid * 4) = o;
        }
        return;
    }
    {
        int w = bid - 16896;
        const float* mb = mask + (size_t)w * 16384;
#pragma unroll
        for (int tile = 0; tile < 4; ++tile) {
            int qt2 = tile >> 1, kt2 = tile & 1;
            int i = qt2 * 32 + il;
            int m0 = kt2 * 32 + ml0;
            float2 mv01 = *(const float2*)(mb + i * 128 + m0);
            float2 mv23 = *(const float2*)(mb + i * 128 + m0 + 8);
            *(float4*)(g_mmf + ((size_t)w * 4 + tile) * 1024 + tid * 4) =
                make_float4(mv01.x, mv01.y, mv23.x, mv23.y);
        }
    }
}

// ---------------- mma / ldsm / cp.async macros ------------------------------
#define MMA_BF16(d, a, b0r, b1r) \
    asm volatile("mma.sync.aligned.m16n8k16.row.col.f32.bf16.bf16.f32 " \
        "{%0,%1,%2,%3},{%4,%5,%6,%7},{%8,%9},{%0,%1,%2,%3};" \
        : "+f"(d[0]), "+f"(d[1]), "+f"(d[2]), "+f"(d[3]) \
        : "r"(a[0]), "r"(a[1]), "r"(a[2]), "r"(a[3]), "r"(b0r), "r"(b1r))

#define MMA_F16(d, a, b0r, b1r) \
    asm volatile("mma.sync.aligned.m16n8k16.row.col.f32.f16.f16.f32 " \
        "{%0,%1,%2,%3},{%4,%5,%6,%7},{%8,%9},{%0,%1,%2,%3};" \
        : "+f"(d[0]), "+f"(d[1]), "+f"(d[2]), "+f"(d[3]) \
        : "r"(a[0]), "r"(a[1]), "r"(a[2]), "r"(a[3]), "r"(b0r), "r"(b1r))

#define LDSM4(r0, r1, r2, r3, addr) \
    asm volatile("ldmatrix.sync.aligned.m8n8.x4.shared.b16 {%0,%1,%2,%3}, [%4];" \
        : "=r"(r0), "=r"(r1), "=r"(r2), "=r"(r3) : "r"(addr))

#define CP16(dst, src) \
    asm volatile("cp.async.cg.shared.global [%0], [%1], 16;" :: "r"(dst), "l"(src))

#define CVT_F16X2(d, hi, lo) \
    asm("cvt.rn.f16x2.f32 %0, %1, %2;" : "=r"(d) : "f"(hi), "f"(lo))

#define PITCH 72
#define STAGE_ELEMS (128 * PITCH)
#define NSTAGE 3

// ---------------- generic GEMM mainloop as a macro body ----------------------
#define GEMM_MAIN(KTOT)                                                           \
    extern __shared__ __nv_bfloat16 smem[];                                       \
    __nv_bfloat16* As = smem;                                                     \
    __nv_bfloat16* Bs = smem + NSTAGE * STAGE_ELEMS;                              \
    const int tid = threadIdx.x;                                                  \
    const int lane = tid & 31, wid = tid >> 5;                                    \
    const int wm = (wid & 1) * 64, wn = (wid >> 1) * 32;                          \
    const int g = lane >> 2, tg = lane & 3;                                       \
    const size_t row0 = (size_t)blockIdx.y * 128;                                 \
    const int col0 = blockIdx.x * 128;                                            \
    constexpr int NC = (KTOT) / 64;                                               \
    const int ldr = tid >> 1;                                                     \
    const int ldu = (tid & 1) * 4;                                                \
    float acc[4][4][4] = {};                                                      \
    const int a_row = wm + (lane & 15);                                           \
    const int a_col = (lane >> 4) * 8;                                            \
    const int bq = lane >> 3;                                                     \
    const int b_row = wn + ((bq >> 1) * 8) + (lane & 7);                          \
    const int b_col = (bq & 1) * 8;                                               \
    LOAD_STAGE(0, 0, KTOT);                                                       \
    LOAD_STAGE(1, 1, KTOT);                                                       \
    _Pragma("unroll")                                                             \
    for (int kc = 0; kc < NC; ++kc) {                                             \
        const int cur = kc % NSTAGE;                                              \
        if (kc + 2 < NC) { asm volatile("cp.async.wait_group 1;"); }              \
        else             { asm volatile("cp.async.wait_group 0;"); }              \
        __syncthreads();                                                          \
        if (kc + 2 < NC) LOAD_STAGE(kc + 2, (kc + 2) % NSTAGE, KTOT);             \
        const __nv_bfloat16* Ad = As + cur * STAGE_ELEMS;                         \
        const __nv_bfloat16* Bd = Bs + cur * STAGE_ELEMS;                         \
        _Pragma("unroll")                                                         \
        for (int ks = 0; ks < 4; ++ks) {                                          \
            const int kb = ks * 16;                                               \
            uint32_t a[4][4], b[2][4];                                            \
            _Pragma("unroll")                                                     \
            for (int mt = 0; mt < 4; ++mt) {                                      \
                unsigned ad = (unsigned)__cvta_generic_to_shared(                 \
                    Ad + (a_row + mt * 16) * PITCH + kb + a_col);                 \
                LDSM4(a[mt][0], a[mt][1], a[mt][2], a[mt][3], ad);                \
            }                                                                     \
            _Pragma("unroll")                                                     \
            for (int p = 0; p < 2; ++p) {                                         \
                unsigned bd = (unsigned)__cvta_generic_to_shared(                 \
                    Bd + (b_row + p * 16) * PITCH + kb + b_col);                  \
                LDSM4(b[p][0], b[p][1], b[p][2], b[p][3], bd);                    \
            }                                                                     \
            _Pragma("unroll")                                                     \
            for (int mt = 0; mt < 4; ++mt)                                        \
                _Pragma("unroll")                                                 \
                for (int nt = 0; nt < 4; ++nt)                                    \
                    MMA_BF16(acc[mt][nt], a[mt], b[nt >> 1][(nt & 1) * 2],        \
                             b[nt >> 1][(nt & 1) * 2 + 1]);                       \
        }                                                                         \
        __syncthreads();                                                          \
    }

#define LOAD_STAGE(kc, s, KTOT)                                                  \
    {                                                                            \
        const __nv_bfloat16* Ab = A + (row0 + ldr) * (KTOT) + (kc) * 64;         \
        const __nv_bfloat16* Wb = W + (size_t)(col0 + ldr) * (KTOT) + (kc) * 64; \
        __nv_bfloat16* Ad = As + (s) * STAGE_ELEMS + ldr * PITCH;                \
        __nv_bfloat16* Bd = Bs + (s) * STAGE_ELEMS + ldr * PITCH;                \
        _Pragma("unroll")                                                        \
        for (int u = 0; u < 4; ++u) {                                            \
            unsigned da = (unsigned)__cvta_generic_to_shared(Ad + (ldu + u) * 8);\
            CP16(da, Ab + (ldu + u) * 8);                                        \
            unsigned db = (unsigned)__cvta_generic_to_shared(Bd + (ldu + u) * 8);\
            CP16(db, Wb + (ldu + u) * 8);                                        \
        }                                                                        \
        asm volatile("cp.async.commit_group;");                                  \
    }

// ---- QKV GEMM: epilogue writes attention-ready Q/K/V operands --------------
__global__ void __launch_bounds__(256) qkv_gemm(
    const __nv_bfloat16* __restrict__ A, const __nv_bfloat16* __restrict__ W,
    ush* __restrict__ q3, ush* __restrict__ k3, ush* __restrict__ vt)
{
    GEMM_MAIN(384)

    const int b = blockIdx.y;     // window (row block == window)
#pragma unroll
    for (int mt = 0; mt < 4; ++mt) {
#pragma unroll
        for (int nt = 0; nt < 4; ++nt) {
            const int c = wn + nt * 8 + 2 * tg;       // 0..127 within part
            const int hh = c >> 4, d = c & 15;
            const int r = wm + mt * 16 + g;
            if (col0 == 0) {                           // Q: A-side triplets x0.25
                unsigned tb[3];
                size_t o = ((size_t)(b * 8 + hh) * 128 + r) * 48 + 3 * d;
                trip2(acc[mt][nt][0] * 0.25f, acc[mt][nt][1] * 0.25f, tb);
                ((unsigned*)(q3 + o))[0] = tb[0];
                ((unsigned*)(q3 + o))[1] = tb[1];
                ((unsigned*)(q3 + o))[2] = tb[2];
                trip2(acc[mt][nt][2] * 0.25f, acc[mt][nt][3] * 0.25f, tb);
                ((unsigned*)(q3 + o + 48 * 8))[0] = tb[0];
                ((unsigned*)(q3 + o + 48 * 8))[1] = tb[1];
                ((unsigned*)(q3 + o + 48 * 8))[2] = tb[2];
            } else if (col0 == 128) {                  // K: B-side triplets
                unsigned tb[3];
                size_t o = ((size_t)(b * 8 + hh) * 128 + r) * 48 + 3 * d;
                trip2B(acc[mt][nt][0], acc[mt][nt][1], tb);
                ((unsigned*)(k3 + o))[0] = tb[0];
                ((unsigned*)(k3 + o))[1] = tb[1];
                ((unsigned*)(k3 + o))[2] = tb[2];
                trip2B(acc[mt][nt][2], acc[mt][nt][3], tb);
                ((unsigned*)(k3 + o + 48 * 8))[0] = tb[0];
                ((unsigned*)(k3 + o + 48 * 8))[1] = tb[1];
                ((unsigned*)(k3 + o + 48 * 8))[2] = tb[2];
            } else {                                   // V: fp16 transposed [d][m]
                ush* vb = vt + (size_t)(b * 8 + hh) * 16 * 128;
                __half v0 = __float2half_rn(acc[mt][nt][0]);
                __half v1 = __float2half_rn(acc[mt][nt][1]);
                __half v2 = __float2half_rn(acc[mt][nt][2]);
                __half v3 = __float2half_rn(acc[mt][nt][3]);
                vb[d * 128 + r]             = *(ush*)&v0;
                vb[(d + 1) * 128 + r]       = *(ush*)&v1;
                vb[d * 128 + r + 8]         = *(ush*)&v2;
                vb[(d + 1) * 128 + r + 8]   = *(ush*)&v3;
            }
        }
    }
}

// ---- projection GEMM (unchanged epilogue) ----------------------------------
__global__ void __launch_bounds__(256) proj_gemm(
    const __nv_bfloat16* __restrict__ A, const __nv_bfloat16* __restrict__ W,
    const float* __restrict__ bvec, float* __restrict__ C)
{
    GEMM_MAIN(768)
#pragma unroll
    for (int mt = 0; mt < 4; ++mt) {
#pragma unroll
        for (int nt = 0; nt < 4; ++nt) {
            size_t row = row0 + wm + mt * 16 + g;
            int col = col0 + wn + nt * 8 + 2 * tg;
            float b0 = bvec[col], b1 = bvec[col + 1];
            *(float2*)&C[row * 128 + col] =
                make_float2(acc[mt][nt][0] + b0, acc[mt][nt][1] + b1);
            *(float2*)&C[(row + 8) * 128 + col] =
                make_float2(acc[mt][nt][2] + b0, acc[mt][nt][3] + b1);
        }
    }
}

// ---------------- tensor-core attention --------------------------------------
// operands pre-converted by qkv_gemm; prologue is pure cp.async.
#define PQ 56
#define PVH 136
#define ATTN_SMEM ((2 * 128 * PQ + 16 * PVH) * 2)

__global__ void __launch_bounds__(128) attn_tc()
{
    extern __shared__ __nv_bfloat16 sm[];
    __nv_bfloat16* Qs = sm;
    __nv_bfloat16* Ks = sm + 128 * PQ;
    ush* VtH = (ush*)(sm + 2 * 128 * PQ);

    const int b = blockIdx.x;
    const bool self = blockIdx.y < 8;
    const int h = self ? blockIdx.y : blockIdx.y - 8;
    const int tid = threadIdx.x, lane = tid & 31, wid = tid >> 5;

    const ush* q3 = (self ? g_q3s : g_q3m) + (size_t)(b * 8 + h) * 128 * 48;
    const ush* k3 = (self ? g_k3s : g_k3m) + (size_t)(b * 8 + h) * 128 * 48;
    const ush* vt = (self ? g_vts : g_vtm) + (size_t)(b * 8 + h) * 16 * 128;

    // ---- coalesced cp.async staging ----
    {
        const int qsrc = self ? tid : ((tid < 64) ? 64 + tid : tid - 64);
#pragma unroll
        for (int u = 0; u < 6; ++u) {
            unsigned dq = (unsigned)__cvta_generic_to_shared(Qs + tid * PQ + u * 8);
            CP16(dq, q3 + qsrc * 48 + u * 8);
            unsigned dk = (unsigned)__cvta_generic_to_shared(Ks + tid * PQ + u * 8);
            CP16(dk, k3 + tid * 48 + u * 8);
        }
#pragma unroll
        for (int u = 0; u < 2; ++u) {
            int ch = tid + u * 128;                  // 256 chunks of 16B
            unsigned dv = (unsigned)__cvta_generic_to_shared(
                VtH + (ch >> 4) * PVH + (ch & 15) * 8);
            CP16(dv, vt + (ch >> 4) * 128 + (ch & 15) * 8);
        }
        asm volatile("cp.async.commit_group;");
        asm volatile("cp.async.wait_group 0;");
    }
    __syncthreads();

    const int g = lane >> 2, tg = lane & 3;
    const int r0 = wid * 32;
    const int a_row = lane & 15, a_col = (lane >> 4) * 8;
    const int bq = lane >> 3;
    const int b_rsub = ((bq >> 1) * 8) + (lane & 7);
    const int b_col8 = (bq & 1) * 8;

    const int nchunk = self ? 4 : 2;
    const int kb0 = (self || wid < 2) ? 0 : 64;
    const float4* bias_t = self
        ? (const float4*)(g_mbf + (((size_t)h * 512 + (b & 511)) * 16 + wid * 4) * 1024)
        : (const float4*)(g_mmf + ((size_t)(b & 511) * 4 + (wid & 1) * 2) * 1024);

    uint32_t aq[3][2][4];
#pragma unroll
    for (int kt = 0; kt < 3; ++kt)
#pragma unroll
        for (int mt = 0; mt < 2; ++mt) {
            unsigned ad = (unsigned)__cvta_generic_to_shared(
                Qs + (r0 + mt * 16 + a_row) * PQ + kt * 16 + a_col);
            LDSM4(aq[kt][mt][0], aq[kt][mt][1], aq[kt][mt][2], aq[kt][mt][3], ad);
        }

    float accO[2][2][4] = {};
    float rs[4] = {0.f, 0.f, 0.f, 0.f};

    for (int mc = 0; mc < nchunk; ++mc) {
        const int key0 = kb0 + mc * 32;
        float4 f[8];
        const float4* ft = bias_t + (size_t)mc * 256;
#pragma unroll
        for (int q = 0; q < 8; ++q) f[q] = ft[q * 32 + lane];

        float accS[2][4][4] = {};
#pragma unroll
        for (int kt = 0; kt < 3; ++kt) {
            uint32_t bf[2][4];
#pragma unroll
            for (int p = 0; p < 2; ++p) {
                unsigned bd = (unsigned)__cvta_generic_to_shared(
                    Ks + (key0 + p * 16 + b_rsub) * PQ + kt * 16 + b_col8);
                LDSM4(bf[p][0], bf[p][1], bf[p][2], bf[p][3], bd);
            }
#pragma unroll
            for (int mt = 0; mt < 2; ++mt)
#pragma unroll
                for (int nt = 0; nt < 4; ++nt)
                    MMA_BF16(accS[mt][nt], aq[kt][mt], bf[nt >> 1][(nt & 1) * 2],
                             bf[nt >> 1][(nt & 1) * 2 + 1]);
        }
#pragma unroll
        for (int mt = 0; mt < 2; ++mt) {
#pragma unroll
            for (int nt = 0; nt < 4; ++nt) {
                const float* f0 = (const float*)&f[mt * 4 + (nt >> 1)];
                const float* f1 = (const float*)&f[mt * 4 + 2 + (nt >> 1)];
                const int e0 = (nt & 1) * 2;
                float p0 = __expf(accS[mt][nt][0] + f0[e0]);
                float p1 = __expf(accS[mt][nt][1] + f0[e0 + 1]);
                float p2 = __expf(accS[mt][nt][2] + f1[e0]);
                float p3 = __expf(accS[mt][nt][3] + f1[e0 + 1]);
                rs[2 * mt]     += p0 + p1;
                rs[2 * mt + 1] += p2 + p3;
                accS[mt][nt][0] = p0; accS[mt][nt][1] = p1;
                accS[mt][nt][2] = p2; accS[mt][nt][3] = p3;
            }
        }
#pragma unroll
        for (int kt2 = 0; kt2 < 2; ++kt2) {
            uint32_t a2[2][4];
#pragma unroll
            for (int mt = 0; mt < 2; ++mt) {
                CVT_F16X2(a2[mt][0], accS[mt][2 * kt2][1],     accS[mt][2 * kt2][0]);
                CVT_F16X2(a2[mt][1], accS[mt][2 * kt2][3],     accS[mt][2 * kt2][2]);
                CVT_F16X2(a2[mt][2], accS[mt][2 * kt2 + 1][1], accS[mt][2 * kt2 + 1][0]);
                CVT_F16X2(a2[mt][3], accS[mt][2 * kt2 + 1][3], accS[mt][2 * kt2 + 1][2]);
            }
            uint32_t b2[4];
            unsigned bd = (unsigned)__cvta_generic_to_shared(
                VtH + b_rsub * PVH + key0 + kt2 * 16 + b_col8);
            LDSM4(b2[0], b2[1], b2[2], b2[3], bd);
#pragma unroll
            for (int mt = 0; mt < 2; ++mt) {
                MMA_F16(accO[mt][0], a2[mt], b2[0], b2[1]);
                MMA_F16(accO[mt][1], a2[mt], b2[2], b2[3]);
            }
        }
    }

#pragma unroll
    for (int s = 0; s < 4; ++s) {
        rs[s] += __shfl_xor_sync(0xffffffffu, rs[s], 1);
        rs[s] += __shfl_xor_sync(0xffffffffu, rs[s], 2);
    }
    float inv[4];
#pragma unroll
    for (int s = 0; s < 4; ++s) inv[s] = 1.f / rs[s];

    const int cbase = self ? 384 : 0;
#pragma unroll
    for (int mt = 0; mt < 2; ++mt) {
#pragma unroll
        for (int nt2 = 0; nt2 < 2; ++nt2) {
            const int d0 = nt2 * 8 + 2 * tg;
            const int rA = r0 + mt * 16 + g;
            unsigned tb[3];
            trip2(accO[mt][nt2][0] * inv[2 * mt], accO[mt][nt2][1] * inv[2 * mt], tb);
            unsigned* oA = (unsigned*)(g_concat3 +
                ((size_t)b * NTOK + rA) * 768 + cbase + (h * HD + d0) * 3);
            oA[0] = tb[0]; oA[1] = tb[1]; oA[2] = tb[2];
            trip2(accO[mt][nt2][2] * inv[2 * mt + 1], accO[mt][nt2][3] * inv[2 * mt + 1], tb);
            unsigned* oB = (unsigned*)(g_concat3 +
                ((size_t)b * NTOK + rA + 8) * 768 + cbase + (h * HD + d0) * 3);
            oB[0] = tb[0]; oB[1] = tb[1]; oB[2] = tb[2];
        }
    }
}

// ---------------- launch ----------------------------------------------------
extern "C" void kernel_launch(void* const* d_in, const int* in_sizes, int n_in,
                              void* d_out, int out_size)
{
    const float* x         = (const float*)d_in[0];
    const float* mask      = (const float*)d_in[1];
    const float* w_self    = (const float*)d_in[2];
    const float* w_mut     = (const float*)d_in[3];
    const float* w_proj    = (const float*)d_in[4];
    const float* b_proj    = (const float*)d_in[5];
    const float* rpe_table = (const float*)d_in[6];
    const float* pe        = (const float*)d_in[7];
    const int*   rpe_index = (const int*)d_in[8];
    float* out = (float*)d_out;

    ush *xs, *xpes, *cc, *ws, *wm, *wp;
    ush *q3s, *k3s, *vts, *q3m, *k3m, *vtm;
    cudaGetSymbolAddress((void**)&ws, g_ws3);
    cudaGetSymbolAddress((void**)&wm, g_wm3);
    cudaGetSymbolAddress((void**)&wp, g_wp3);
    cudaGetSymbolAddress((void**)&xs, g_xs3);
    cudaGetSymbolAddress((void**)&xpes, g_xpes3);
    cudaGetSymbolAddress((void**)&cc, g_concat3);
    cudaGetSymbolAddress((void**)&q3s, g_q3s);
    cudaGetSymbolAddress((void**)&k3s, g_k3s);
    cudaGetSymbolAddress((void**)&vts, g_vts);
    cudaGetSymbolAddress((void**)&q3m, g_q3m);
    cudaGetSymbolAddress((void**)&k3m, g_k3m);
    cudaGetSymbolAddress((void**)&vtm, g_vtm);

    const int SMEM = 2 * NSTAGE * STAGE_ELEMS * (int)sizeof(__nv_bfloat16); // 110592
    cudaFuncSetAttribute(qkv_gemm, cudaFuncAttributeMaxDynamicSharedMemorySize, SMEM);
    cudaFuncSetAttribute(proj_gemm, cudaFuncAttributeMaxDynamicSharedMemorySize, SMEM);
    cudaFuncSetAttribute(attn_tc, cudaFuncAttributeMaxDynamicSharedMemorySize, ATTN_SMEM);

    // launch 1: all prep
    prep_all<<<17408, 256>>>(x, pe, w_self, w_mut, w_proj, mask, rpe_index, rpe_table);

    // launches 2,3: QKV GEMMs with attention-ready epilogue
    qkv_gemm<<<dim3(3, 1024), 256, SMEM>>>(
        (const __nv_bfloat16*)xs,   (const __nv_bfloat16*)ws, q3s, k3s, vts);
    qkv_gemm<<<dim3(3, 1024), 256, SMEM>>>(
        (const __nv_bfloat16*)xpes, (const __nv_bfloat16*)wm, q3m, k3m, vtm);

    // launch 4: tensor-core attention  (<- ncu capture slot)
    attn_tc<<<dim3(WB, 16), 128, ATTN_SMEM>>>();

    // launch 5: projection (K' = 768)
    proj_gemm<<<dim3(1, 1024), 256, SMEM>>>(
        (const __nv_bfloat16*)cc, (const __nv_bfloat16*)wp, b_proj, out);
}

// round 14
// speedup vs baseline: 1.5403x; 1.0240x over previous
#include <cuda_runtime.h>
#include <cuda_bf16.h>
#include <cuda_fp16.h>
#include <cstddef>
#include <cstdint>

#define WB     1024
#define NTOK   128
#define NHEADS 8
#define HD     16
#define MROWS  (WB * NTOK)          // 131072

typedef unsigned long long ull;
typedef unsigned short ush;

// ---------------- scratch (device globals; no runtime allocation) ----------
__device__ ush g_xs3  [(size_t)MROWS * 384];
__device__ ush g_xpes3[(size_t)MROWS * 384];
__device__ ush g_ws3  [384 * 384];
__device__ ush g_wm3  [384 * 384];
__device__ ush g_wp3  [128 * 768];
// attention-ready operands, written by QKV GEMM epilogue
__device__ ush g_q3s[(size_t)WB * NHEADS * NTOK * 48];  // A-side triplets (x0.25)
__device__ ush g_k3s[(size_t)WB * NHEADS * NTOK * 48];  // B-side triplets
__device__ ush g_vts[(size_t)WB * NHEADS * HD * NTOK];  // fp16, [bh][d][m]
__device__ ush g_q3m[(size_t)WB * NHEADS * NTOK * 48];
__device__ ush g_k3m[(size_t)WB * NHEADS * NTOK * 48];
__device__ ush g_vtm[(size_t)WB * NHEADS * HD * NTOK];
__device__ ush g_concat3[(size_t)MROWS * 768];
// fragment-ordered tables: mask (per window) + rpe bias (per head) + mutual mask
__device__ float g_maskf[(size_t)512 * 16 * 1024];      // [w][tile][1024]   33.5 MB
__device__ float g_rpef [(size_t)NHEADS * 16 * 1024];   // [h][tile][1024]   512 KB
__device__ float g_mmf  [(size_t)512 * 4 * 1024];       // [w][tile2][1024]  8 MB

__device__ __forceinline__ void split_hl(float v, ush& h, ush& l) {
    __nv_bfloat16 hh = __float2bfloat16(v);
    float r = v - __bfloat162float(hh);
    __nv_bfloat16 ll = __float2bfloat16(r);
    h = *(ush*)&hh;
    l = *(ush*)&ll;
}

// A-side pair (h,h,l)(h,h,l)
__device__ __forceinline__ void trip2(float a, float b, unsigned* o) {
    ush h0, l0, h1, l1;
    split_hl(a, h0, l0); split_hl(b, h1, l1);
    o[0] = (unsigned)h0 | ((unsigned)h0 << 16);
    o[1] = (unsigned)l0 | ((unsigned)h1 << 16);
    o[2] = (unsigned)h1 | ((unsigned)l1 << 16);
}
// B-side pair (h,l,h)(h,l,h)
__device__ __forceinline__ void trip2B(float a, float b, unsigned* o) {
    ush h0, l0, h1, l1;
    split_hl(a, h0, l0); split_hl(b, h1, l1);
    o[0] = (unsigned)h0 | ((unsigned)l0 << 16);
    o[1] = (unsigned)h0 | ((unsigned)h1 << 16);
    o[2] = (unsigned)l1 | ((unsigned)h1 << 16);
}

// ---------------- fused prep (ONE launch) -----------------------------------
__global__ void __launch_bounds__(256) prep_all(
    const float* __restrict__ x, const float* __restrict__ pe,
    const float* __restrict__ ws, const float* __restrict__ wm,
    const float* __restrict__ wp, const float* __restrict__ mask,
    const int* __restrict__ rpe_index, const float* __restrict__ rpe_table)
{
    const int bid = blockIdx.x, tid = threadIdx.x;
    if (bid < 512) {
        int i = bid * 256 + tid;
        float v; ush* dst;
        if (i < 49152)       { v = ws[i];          dst = g_ws3 + 3 * i; }
        else if (i < 98304)  { v = wm[i - 49152];  dst = g_wm3 + 3 * (i - 49152); }
        else                 { v = wp[i - 98304];  dst = g_wp3 + 3 * (i - 98304); }
        ush h, l;
        split_hl(v, h, l);
        dst[0] = h; dst[1] = l; dst[2] = h;
        return;
    }
    if (bid < 8704) {
        size_t idx8 = (size_t)(bid - 512) * 256 + tid;
        size_t e0 = idx8 * 8;
        int c = (int)(e0 & 127);
        int t = (int)((e0 >> 7) & 127);
        float4 xv0 = ((const float4*)x)[idx8 * 2];
        float4 xv1 = ((const float4*)x)[idx8 * 2 + 1];
        const float* pp = pe + (t & 63) * 128 + c;
        float xe[8] = {xv0.x, xv0.y, xv0.z, xv0.w, xv1.x, xv1.y, xv1.z, xv1.w};
        ush b0[24], b1[24];
#pragma unroll
        for (int j = 0; j < 8; ++j) {
            ush h, l;
            split_hl(xe[j], h, l);
            b0[3 * j] = h; b0[3 * j + 1] = h; b0[3 * j + 2] = l;
            split_hl(xe[j] + pp[j], h, l);
            b1[3 * j] = h; b1[3 * j + 1] = h; b1[3 * j + 2] = l;
        }
        uint4* d0 = (uint4*)(g_xs3 + 3 * e0);
        uint4* d1 = (uint4*)(g_xpes3 + 3 * e0);
        const uint4* s0 = (const uint4*)b0;
        const uint4* s1 = (const uint4*)b1;
        d0[0] = s0[0]; d0[1] = s0[1]; d0[2] = s0[2];
        d1[0] = s1[0]; d1[1] = s1[1]; d1[2] = s1[2];
        return;
    }
    const int q = tid >> 5, lane = tid & 31, g = lane >> 2, tg = lane & 3;
    const int il = (q >> 2) * 16 + ((q >> 1) & 1) * 8 + g;
    const int ml0 = (q & 1) * 16 + 2 * tg;
    if (bid < 16896) {
        int blin = bid - 8704;
        int w = blin >> 4, tile = blin & 15;
        int qt = tile >> 2, kt = tile & 3;
        int i = qt * 32 + il;
        int m0 = kt * 32 + ml0;
        const float* mrow = mask + (size_t)w * 16384 + i * 128;
        float2 mv01 = *(const float2*)(mrow + m0);
        float2 mv23 = *(const float2*)(mrow + m0 + 8);
        *(float4*)(g_maskf + ((size_t)w * 16 + tile) * 1024 + tid * 4) =
            make_float4(mv01.x, mv01.y, mv23.x, mv23.y);
        if (w == 0) {       // rpe fragment table: per (h, tile) only
            const int* irow = rpe_index + i * 128;
            int2 ix01 = *(const int2*)(irow + m0);
            int2 ix23 = *(const int2*)(irow + m0 + 8);
            float t0[8], t1[8], t2[8], t3[8];
            *(float4*)t0 = *(const float4*)(rpe_table + ix01.x * 8);
            *(float4*)(t0+4) = *(const float4*)(rpe_table + ix01.x * 8 + 4);
            *(float4*)t1 = *(const float4*)(rpe_table + ix01.y * 8);
            *(float4*)(t1+4) = *(const float4*)(rpe_table + ix01.y * 8 + 4);
            *(float4*)t2 = *(const float4*)(rpe_table + ix23.x * 8);
            *(float4*)(t2+4) = *(const float4*)(rpe_table + ix23.x * 8 + 4);
            *(float4*)t3 = *(const float4*)(rpe_table + ix23.y * 8);
            *(float4*)(t3+4) = *(const float4*)(rpe_table + ix23.y * 8 + 4);
#pragma unroll
            for (int h = 0; h < NHEADS; ++h)
                *(float4*)(g_rpef + ((size_t)h * 16 + tile) * 1024 + tid * 4) =
                    make_float4(t0[h], t1[h], t2[h], t3[h]);
        }
        return;
    }
    {
        int w = bid - 16896;
        const float* mb = mask + (size_t)w * 16384;
#pragma unroll
        for (int tile = 0; tile < 4; ++tile) {
            int qt2 = tile >> 1, kt2 = tile & 1;
            int i = qt2 * 32 + il;
            int m0 = kt2 * 32 + ml0;
            float2 mv01 = *(const float2*)(mb + i * 128 + m0);
            float2 mv23 = *(const float2*)(mb + i * 128 + m0 + 8);
            *(float4*)(g_mmf + ((size_t)w * 4 + tile) * 1024 + tid * 4) =
                make_float4(mv01.x, mv01.y, mv23.x, mv23.y);
        }
    }
}

// ---------------- mma / ldsm / cp.async macros ------------------------------
#define MMA_BF16(d, a, b0r, b1r) \
    asm volatile("mma.sync.aligned.m16n8k16.row.col.f32.bf16.bf16.f32 " \
        "{%0,%1,%2,%3},{%4,%5,%6,%7},{%8,%9},{%0,%1,%2,%3};" \
        : "+f"(d[0]), "+f"(d[1]), "+f"(d[2]), "+f"(d[3]) \
        : "r"(a[0]), "r"(a[1]), "r"(a[2]), "r"(a[3]), "r"(b0r), "r"(b1r))

#define MMA_F16(d, a, b0r, b1r) \
    asm volatile("mma.sync.aligned.m16n8k16.row.col.f32.f16.f16.f32 " \
        "{%0,%1,%2,%3},{%4,%5,%6,%7},{%8,%9},{%0,%1,%2,%3};" \
        : "+f"(d[0]), "+f"(d[1]), "+f"(d[2]), "+f"(d[3]) \
        : "r"(a[0]), "r"(a[1]), "r"(a[2]), "r"(a[3]), "r"(b0r), "r"(b1r))

#define LDSM4(r0, r1, r2, r3, addr) \
    asm volatile("ldmatrix.sync.aligned.m8n8.x4.shared.b16 {%0,%1,%2,%3}, [%4];" \
        : "=r"(r0), "=r"(r1), "=r"(r2), "=r"(r3) : "r"(addr))

#define CP16(dst, src) \
    asm volatile("cp.async.cg.shared.global [%0], [%1], 16;" :: "r"(dst), "l"(src))

#define CVT_F16X2(d, hi, lo) \
    asm("cvt.rn.f16x2.f32 %0, %1, %2;" : "=r"(d) : "f"(hi), "f"(lo))

#define PITCH 72
#define STAGE_ELEMS (128 * PITCH)
#define NSTAGE 3

// ---------------- generic GEMM mainloop as a macro body ----------------------
#define GEMM_MAIN(KTOT)                                                           \
    extern __shared__ __nv_bfloat16 smem[];                                       \
    __nv_bfloat16* As = smem;                                                     \
    __nv_bfloat16* Bs = smem + NSTAGE * STAGE_ELEMS;                              \
    const int tid = threadIdx.x;                                                  \
    const int lane = tid & 31, wid = tid >> 5;                                    \
    const int wm = (wid & 1) * 64, wn = (wid >> 1) * 32;                          \
    const int g = lane >> 2, tg = lane & 3;                                       \
    const size_t row0 = (size_t)blockIdx.y * 128;                                 \
    const int col0 = blockIdx.x * 128;                                            \
    constexpr int NC = (KTOT) / 64;                                               \
    const int ldr = tid >> 1;                                                     \
    const int ldu = (tid & 1) * 4;                                                \
    float acc[4][4][4] = {};                                                      \
    const int a_row = wm + (lane & 15);                                           \
    const int a_col = (lane >> 4) * 8;                                            \
    const int bq = lane >> 3;                                                     \
    const int b_row = wn + ((bq >> 1) * 8) + (lane & 7);                          \
    const int b_col = (bq & 1) * 8;                                               \
    LOAD_STAGE(0, 0, KTOT);                                                       \
    LOAD_STAGE(1, 1, KTOT);                                                       \
    _Pragma("unroll")                                                             \
    for (int kc = 0; kc < NC; ++kc) {                                             \
        const int cur = kc % NSTAGE;                                              \
        if (kc + 2 < NC) { asm volatile("cp.async.wait_group 1;"); }              \
        else             { asm volatile("cp.async.wait_group 0;"); }              \
        __syncthreads();                                                          \
        if (kc + 2 < NC) LOAD_STAGE(kc + 2, (kc + 2) % NSTAGE, KTOT);             \
        const __nv_bfloat16* Ad = As + cur * STAGE_ELEMS;                         \
        const __nv_bfloat16* Bd = Bs + cur * STAGE_ELEMS;                         \
        _Pragma("unroll")                                                         \
        for (int ks = 0; ks < 4; ++ks) {                                          \
            const int kb = ks * 16;                                               \
            uint32_t a[4][4], b[2][4];                                            \
            _Pragma("unroll")                                                     \
            for (int mt = 0; mt < 4; ++mt) {                                      \
                unsigned ad = (unsigned)__cvta_generic_to_shared(                 \
                    Ad + (a_row + mt * 16) * PITCH + kb + a_col);                 \
                LDSM4(a[mt][0], a[mt][1], a[mt][2], a[mt][3], ad);                \
            }                                                                     \
            _Pragma("unroll")                                                     \
            for (int p = 0; p < 2; ++p) {                                         \
                unsigned bd = (unsigned)__cvta_generic_to_shared(                 \
                    Bd + (b_row + p * 16) * PITCH + kb + b_col);                  \
                LDSM4(b[p][0], b[p][1], b[p][2], b[p][3], bd);                    \
            }                                                                     \
            _Pragma("unroll")                                                     \
            for (int mt = 0; mt < 4; ++mt)                                        \
                _Pragma("unroll")                                                 \
                for (int nt = 0; nt < 4; ++nt)                                    \
                    MMA_BF16(acc[mt][nt], a[mt], b[nt >> 1][(nt & 1) * 2],        \
                             b[nt >> 1][(nt & 1) * 2 + 1]);                       \
        }                                                                         \
        __syncthreads();                                                          \
    }

#define LOAD_STAGE(kc, s, KTOT)                                                  \
    {                                                                            \
        const __nv_bfloat16* Ab = A + (row0 + ldr) * (KTOT) + (kc) * 64;         \
        const __nv_bfloat16* Wb = W + (size_t)(col0 + ldr) * (KTOT) + (kc) * 64; \
        __nv_bfloat16* Ad = As + (s) * STAGE_ELEMS + ldr * PITCH;                \
        __nv_bfloat16* Bd = Bs + (s) * STAGE_ELEMS + ldr * PITCH;                \
        _Pragma("unroll")                                                        \
        for (int u = 0; u < 4; ++u) {                                            \
            unsigned da = (unsigned)__cvta_generic_to_shared(Ad + (ldu + u) * 8);\
            CP16(da, Ab + (ldu + u) * 8);                                        \
            unsigned db = (unsigned)__cvta_generic_to_shared(Bd + (ldu + u) * 8);\
            CP16(db, Wb + (ldu + u) * 8);                                        \
        }                                                                        \
        asm volatile("cp.async.commit_group;");                                  \
    }

// ---- QKV GEMM: epilogue writes attention-ready Q/K/V operands --------------
__global__ void __launch_bounds__(256) qkv_gemm(
    const __nv_bfloat16* __restrict__ A, const __nv_bfloat16* __restrict__ W,
    ush* __restrict__ q3, ush* __restrict__ k3, ush* __restrict__ vt)
{
    GEMM_MAIN(384)

    const int b = blockIdx.y;
#pragma unroll
    for (int mt = 0; mt < 4; ++mt) {
#pragma unroll
        for (int nt = 0; nt < 4; ++nt) {
            const int c = wn + nt * 8 + 2 * tg;
            const int hh = c >> 4, d = c & 15;
            const int r = wm + mt * 16 + g;
            if (col0 == 0) {                           // Q: A-side triplets x0.25
                unsigned tb[3];
                size_t o = ((size_t)(b * 8 + hh) * 128 + r) * 48 + 3 * d;
                trip2(acc[mt][nt][0] * 0.25f, acc[mt][nt][1] * 0.25f, tb);
                ((unsigned*)(q3 + o))[0] = tb[0];
                ((unsigned*)(q3 + o))[1] = tb[1];
                ((unsigned*)(q3 + o))[2] = tb[2];
                trip2(acc[mt][nt][2] * 0.25f, acc[mt][nt][3] * 0.25f, tb);
                ((unsigned*)(q3 + o + 48 * 8))[0] = tb[0];
                ((unsigned*)(q3 + o + 48 * 8))[1] = tb[1];
                ((unsigned*)(q3 + o + 48 * 8))[2] = tb[2];
            } else if (col0 == 128) {                  // K: B-side triplets
                unsigned tb[3];
                size_t o = ((size_t)(b * 8 + hh) * 128 + r) * 48 + 3 * d;
                trip2B(acc[mt][nt][0], acc[mt][nt][1], tb);
                ((unsigned*)(k3 + o))[0] = tb[0];
                ((unsigned*)(k3 + o))[1] = tb[1];
                ((unsigned*)(k3 + o))[2] = tb[2];
                trip2B(acc[mt][nt][2], acc[mt][nt][3], tb);
                ((unsigned*)(k3 + o + 48 * 8))[0] = tb[0];
                ((unsigned*)(k3 + o + 48 * 8))[1] = tb[1];
                ((unsigned*)(k3 + o + 48 * 8))[2] = tb[2];
            } else {                                   // V: fp16 transposed [d][m]
                ush* vb = vt + (size_t)(b * 8 + hh) * 16 * 128;
                __half v0 = __float2half_rn(acc[mt][nt][0]);
                __half v1 = __float2half_rn(acc[mt][nt][1]);
                __half v2 = __float2half_rn(acc[mt][nt][2]);
                __half v3 = __float2half_rn(acc[mt][nt][3]);
                vb[d * 128 + r]             = *(ush*)&v0;
                vb[(d + 1) * 128 + r]       = *(ush*)&v1;
                vb[d * 128 + r + 8]         = *(ush*)&v2;
                vb[(d + 1) * 128 + r + 8]   = *(ush*)&v3;
            }
        }
    }
}

// ---- projection GEMM -------------------------------------------------------
__global__ void __launch_bounds__(256) proj_gemm(
    const __nv_bfloat16* __restrict__ A, const __nv_bfloat16* __restrict__ W,
    const float* __restrict__ bvec, float* __restrict__ C)
{
    GEMM_MAIN(768)
#pragma unroll
    for (int mt = 0; mt < 4; ++mt) {
#pragma unroll
        for (int nt = 0; nt < 4; ++nt) {
            size_t row = row0 + wm + mt * 16 + g;
            int col = col0 + wn + nt * 8 + 2 * tg;
            float b0 = bvec[col], b1 = bvec[col + 1];
            *(float2*)&C[row * 128 + col] =
                make_float2(acc[mt][nt][0] + b0, acc[mt][nt][1] + b1);
            *(float2*)&C[(row + 8) * 128 + col] =
                make_float2(acc[mt][nt][2] + b0, acc[mt][nt][3] + b1);
        }
    }
}

// ---------------- tensor-core attention --------------------------------------
#define PQ 56
#define PVH 136
#define ATTN_SMEM ((2 * 128 * PQ + 16 * PVH) * 2)

__global__ void __launch_bounds__(128) attn_tc()
{
    extern __shared__ __nv_bfloat16 sm[];
    __nv_bfloat16* Qs = sm;
    __nv_bfloat16* Ks = sm + 128 * PQ;
    ush* VtH = (ush*)(sm + 2 * 128 * PQ);

    const int b = blockIdx.x;
    const bool self = blockIdx.y < 8;
    const int h = self ? blockIdx.y : blockIdx.y - 8;
    const int tid = threadIdx.x, lane = tid & 31, wid = tid >> 5;

    const ush* q3 = (self ? g_q3s : g_q3m) + (size_t)(b * 8 + h) * 128 * 48;
    const ush* k3 = (self ? g_k3s : g_k3m) + (size_t)(b * 8 + h) * 128 * 48;
    const ush* vt = (self ? g_vts : g_vtm) + (size_t)(b * 8 + h) * 16 * 128;

    // ---- coalesced cp.async staging ----
    {
        const int qsrc = self ? tid : ((tid < 64) ? 64 + tid : tid - 64);
#pragma unroll
        for (int u = 0; u < 6; ++u) {
            unsigned dq = (unsigned)__cvta_generic_to_shared(Qs + tid * PQ + u * 8);
            CP16(dq, q3 + qsrc * 48 + u * 8);
            unsigned dk = (unsigned)__cvta_generic_to_shared(Ks + tid * PQ + u * 8);
            CP16(dk, k3 + tid * 48 + u * 8);
        }
#pragma unroll
        for (int u = 0; u < 2; ++u) {
            int ch = tid + u * 128;
            unsigned dv = (unsigned)__cvta_generic_to_shared(
                VtH + (ch >> 4) * PVH + (ch & 15) * 8);
            CP16(dv, vt + (ch >> 4) * 128 + (ch & 15) * 8);
        }
        asm volatile("cp.async.commit_group;");
        asm volatile("cp.async.wait_group 0;");
    }
    __syncthreads();

    const int g = lane >> 2, tg = lane & 3;
    const int r0 = wid * 32;
    const int a_row = lane & 15, a_col = (lane >> 4) * 8;
    const int bq = lane >> 3;
    const int b_rsub = ((bq >> 1) * 8) + (lane & 7);
    const int b_col8 = (bq & 1) * 8;

    const int nchunk = self ? 4 : 2;
    const int kb0 = (self || wid < 2) ? 0 : 64;
    const float4* mask_t = self
        ? (const float4*)(g_maskf + ((size_t)(b & 511) * 16 + wid * 4) * 1024)
        : (const float4*)(g_mmf + ((size_t)(b & 511) * 4 + (wid & 1) * 2) * 1024);
    const float4* rpe_t = (const float4*)(g_rpef + ((size_t)h * 16 + wid * 4) * 1024);

    uint32_t aq[3][2][4];
#pragma unroll
    for (int kt = 0; kt < 3; ++kt)
#pragma unroll
        for (int mt = 0; mt < 2; ++mt) {
            unsigned ad = (unsigned)__cvta_generic_to_shared(
                Qs + (r0 + mt * 16 + a_row) * PQ + kt * 16 + a_col);
            LDSM4(aq[kt][mt][0], aq[kt][mt][1], aq[kt][mt][2], aq[kt][mt][3], ad);
        }

    float accO[2][2][4] = {};
    float rs[4] = {0.f, 0.f, 0.f, 0.f};

    for (int mc = 0; mc < nchunk; ++mc) {
        const int key0 = kb0 + mc * 32;
        float4 f[8];
        {
            const float4* mt4 = mask_t + (size_t)mc * 256;
#pragma unroll
            for (int q = 0; q < 8; ++q) f[q] = mt4[q * 32 + lane];
            if (self) {
                const float4* rt4 = rpe_t + (size_t)mc * 256;
#pragma unroll
                for (int q = 0; q < 8; ++q) {
                    float4 r = rt4[q * 32 + lane];
                    f[q].x += r.x; f[q].y += r.y; f[q].z += r.z; f[q].w += r.w;
                }
            }
        }

        float accS[2][4][4] = {};
#pragma unroll
        for (int kt = 0; kt < 3; ++kt) {
            uint32_t bf[2][4];
#pragma unroll
            for (int p = 0; p < 2; ++p) {
                unsigned bd = (unsigned)__cvta_generic_to_shared(
                    Ks + (key0 + p * 16 + b_rsub) * PQ + kt * 16 + b_col8);
                LDSM4(bf[p][0], bf[p][1], bf[p][2], bf[p][3], bd);
            }
#pragma unroll
            for (int mt = 0; mt < 2; ++mt)
#pragma unroll
                for (int nt = 0; nt < 4; ++nt)
                    MMA_BF16(accS[mt][nt], aq[kt][mt], bf[nt >> 1][(nt & 1) * 2],
                             bf[nt >> 1][(nt & 1) * 2 + 1]);
        }
#pragma unroll
        for (int mt = 0; mt < 2; ++mt) {
#pragma unroll
            for (int nt = 0; nt < 4; ++nt) {
                const float* f0 = (const float*)&f[mt * 4 + (nt >> 1)];
                const float* f1 = (const float*)&f[mt * 4 + 2 + (nt >> 1)];
                const int e0 = (nt & 1) * 2;
                float p0 = __expf(accS[mt][nt][0] + f0[e0]);
                float p1 = __expf(accS[mt][nt][1] + f0[e0 + 1]);
                float p2 = __expf(accS[mt][nt][2] + f1[e0]);
                float p3 = __expf(accS[mt][nt][3] + f1[e0 + 1]);
                rs[2 * mt]     += p0 + p1;
                rs[2 * mt + 1] += p2 + p3;
                accS[mt][nt][0] = p0; accS[mt][nt][1] = p1;
                accS[mt][nt][2] = p2; accS[mt][nt][3] = p3;
            }
        }
#pragma unroll
        for (int kt2 = 0; kt2 < 2; ++kt2) {
            uint32_t a2[2][4];
#pragma unroll
            for (int mt = 0; mt < 2; ++mt) {
                CVT_F16X2(a2[mt][0], accS[mt][2 * kt2][1],     accS[mt][2 * kt2][0]);
                CVT_F16X2(a2[mt][1], accS[mt][2 * kt2][3],     accS[mt][2 * kt2][2]);
                CVT_F16X2(a2[mt][2], accS[mt][2 * kt2 + 1][1], accS[mt][2 * kt2 + 1][0]);
                CVT_F16X2(a2[mt][3], accS[mt][2 * kt2 + 1][3], accS[mt][2 * kt2 + 1][2]);
            }
            uint32_t b2[4];
            unsigned bd = (unsigned)__cvta_generic_to_shared(
                VtH + b_rsub * PVH + key0 + kt2 * 16 + b_col8);
            LDSM4(b2[0], b2[1], b2[2], b2[3], bd);
#pragma unroll
            for (int mt = 0; mt < 2; ++mt) {
                MMA_F16(accO[mt][0], a2[mt], b2[0], b2[1]);
                MMA_F16(accO[mt][1], a2[mt], b2[2], b2[3]);
            }
        }
    }

#pragma unroll
    for (int s = 0; s < 4; ++s) {
        rs[s] += __shfl_xor_sync(0xffffffffu, rs[s], 1);
        rs[s] += __shfl_xor_sync(0xffffffffu, rs[s], 2);
    }
    float inv[4];
#pragma unroll
    for (int s = 0; s < 4; ++s) inv[s] = 1.f / rs[s];

    const int cbase = self ? 384 : 0;
#pragma unroll
    for (int mt = 0; mt < 2; ++mt) {
#pragma unroll
        for (int nt2 = 0; nt2 < 2; ++nt2) {
            const int d0 = nt2 * 8 + 2 * tg;
            const int rA = r0 + mt * 16 + g;
            unsigned tb[3];
            trip2(accO[mt][nt2][0] * inv[2 * mt], accO[mt][nt2][1] * inv[2 * mt], tb);
            unsigned* oA = (unsigned*)(g_concat3 +
                ((size_t)b * NTOK + rA) * 768 + cbase + (h * HD + d0) * 3);
            oA[0] = tb[0]; oA[1] = tb[1]; oA[2] = tb[2];
            trip2(accO[mt][nt2][2] * inv[2 * mt + 1], accO[mt][nt2][3] * inv[2 * mt + 1], tb);
            unsigned* oB = (unsigned*)(g_concat3 +
                ((size_t)b * NTOK + rA + 8) * 768 + cbase + (h * HD + d0) * 3);
            oB[0] = tb[0]; oB[1] = tb[1]; oB[2] = tb[2];
        }
    }
}

// ---------------- launch ----------------------------------------------------
extern "C" void kernel_launch(void* const* d_in, const int* in_sizes, int n_in,
                              void* d_out, int out_size)
{
    const float* x         = (const float*)d_in[0];
    const float* mask      = (const float*)d_in[1];
    const float* w_self    = (const float*)d_in[2];
    const float* w_mut     = (const float*)d_in[3];
    const float* w_proj    = (const float*)d_in[4];
    const float* b_proj    = (const float*)d_in[5];
    const float* rpe_table = (const float*)d_in[6];
    const float* pe        = (const float*)d_in[7];
    const int*   rpe_index = (const int*)d_in[8];
    float* out = (float*)d_out;

    ush *xs, *xpes, *cc, *ws, *wm, *wp;
    ush *q3s, *k3s, *vts, *q3m, *k3m, *vtm;
    cudaGetSymbolAddress((void**)&ws, g_ws3);
    cudaGetSymbolAddress((void**)&wm, g_wm3);
    cudaGetSymbolAddress((void**)&wp, g_wp3);
    cudaGetSymbolAddress((void**)&xs, g_xs3);
    cudaGetSymbolAddress((void**)&xpes, g_xpes3);
    cudaGetSymbolAddress((void**)&cc, g_concat3);
    cudaGetSymbolAddress((void**)&q3s, g_q3s);
    cudaGetSymbolAddress((void**)&k3s, g_k3s);
    cudaGetSymbolAddress((void**)&vts, g_vts);
    cudaGetSymbolAddress((void**)&q3m, g_q3m);
    cudaGetSymbolAddress((void**)&k3m, g_k3m);
    cudaGetSymbolAddress((void**)&vtm, g_vtm);

    const int SMEM = 2 * NSTAGE * STAGE_ELEMS * (int)sizeof(__nv_bfloat16); // 110592
    cudaFuncSetAttribute(qkv_gemm, cudaFuncAttributeMaxDynamicSharedMemorySize, SMEM);
    cudaFuncSetAttribute(proj_gemm, cudaFuncAttributeMaxDynamicSharedMemorySize, SMEM);
    cudaFuncSetAttribute(attn_tc, cudaFuncAttributeMaxDynamicSharedMemorySize, ATTN_SMEM);

    // launch 1: all prep
    prep_all<<<17408, 256>>>(x, pe, w_self, w_mut, w_proj, mask, rpe_index, rpe_table);

    // launches 2,3: QKV GEMMs with attention-ready epilogue
    qkv_gemm<<<dim3(3, 1024), 256, SMEM>>>(
        (const __nv_bfloat16*)xs,   (const __nv_bfloat16*)ws, q3s, k3s, vts);
    qkv_gemm<<<dim3(3, 1024), 256, SMEM>>>(
        (const __nv_bfloat16*)xpes, (const __nv_bfloat16*)wm, q3m, k3m, vtm);

    // launch 4: tensor-core attention  (<- ncu capture slot)
    attn_tc<<<dim3(WB, 16), 128, ATTN_SMEM>>>();

    // launch 5: projection (K' = 768)
    proj_gemm<<<dim3(1, 1024), 256, SMEM>>>(
        (const __nv_bfloat16*)cc, (const __nv_bfloat16*)wp, b_proj, out);
}

// round 15
// speedup vs baseline: 1.5882x; 1.0311x over previous
#include <cuda_runtime.h>
#include <cuda_bf16.h>
#include <cuda_fp16.h>
#include <cstddef>
#include <cstdint>

#define WB     1024
#define NTOK   128
#define NHEADS 8
#define HD     16
#define MROWS  (WB * NTOK)          // 131072

typedef unsigned long long ull;
typedef unsigned short ush;

// ---------------- scratch (device globals; no runtime allocation) ----------
__device__ ush g_xs3 [(size_t)MROWS * 384];             // x split (A-side), shared
__device__ ush g_ws3 [384 * 384];
__device__ ush g_wm3 [384 * 384];
__device__ ush g_wp2 [128 * 512];                       // w_proj fp16 (h,l) pairs
__device__ float g_peW[64 * 384];                       // pe @ w_mut^T
// attention-ready operands, written by QKV GEMM epilogue
__device__ ush g_q3s[(size_t)WB * NHEADS * NTOK * 48];
__device__ ush g_k3s[(size_t)WB * NHEADS * NTOK * 48];
__device__ ush g_vts[(size_t)WB * NHEADS * HD * NTOK];
__device__ ush g_q3m[(size_t)WB * NHEADS * NTOK * 48];
__device__ ush g_k3m[(size_t)WB * NHEADS * NTOK * 48];
__device__ ush g_vtm[(size_t)WB * NHEADS * HD * NTOK];
__device__ ush g_concat2h[(size_t)MROWS * 512];         // fp16 (c,c) pairs, K'=512
// fragment-ordered tables
__device__ float g_maskf[(size_t)512 * 16 * 1024];
__device__ float g_rpef [(size_t)NHEADS * 16 * 1024];
__device__ float g_mmf  [(size_t)512 * 4 * 1024];

__device__ __forceinline__ void split_hl(float v, ush& h, ush& l) {
    __nv_bfloat16 hh = __float2bfloat16(v);
    float r = v - __bfloat162float(hh);
    __nv_bfloat16 ll = __float2bfloat16(r);
    h = *(ush*)&hh;
    l = *(ush*)&ll;
}

// A-side pair (h,h,l)(h,h,l)
__device__ __forceinline__ void trip2(float a, float b, unsigned* o) {
    ush h0, l0, h1, l1;
    split_hl(a, h0, l0); split_hl(b, h1, l1);
    o[0] = (unsigned)h0 | ((unsigned)h0 << 16);
    o[1] = (unsigned)l0 | ((unsigned)h1 << 16);
    o[2] = (unsigned)h1 | ((unsigned)l1 << 16);
}
// B-side pair (h,l,h)(h,l,h)
__device__ __forceinline__ void trip2B(float a, float b, unsigned* o) {
    ush h0, l0, h1, l1;
    split_hl(a, h0, l0); split_hl(b, h1, l1);
    o[0] = (unsigned)h0 | ((unsigned)l0 << 16);
    o[1] = (unsigned)h0 | ((unsigned)h1 << 16);
    o[2] = (unsigned)l1 | ((unsigned)h1 << 16);
}

__device__ __forceinline__ unsigned dup_h(float v) {
    __half hv = __float2half_rn(v);
    unsigned u = *(ush*)&hv;
    return u | (u << 16);
}

// ---------------- fused prep (ONE launch) -----------------------------------
// [0,512):       weight splits (ws3/wm3 triplets, wp2 fp16 pairs)
// [512,8704):    x split (A-side h,h,l)
// [8704,16896):  maskf + rpef(w==0)
// [16896,17408): mmf
// [17408,17504): peW = pe @ w_mut^T
__global__ void __launch_bounds__(256) prep_all(
    const float* __restrict__ x, const float* __restrict__ pe,
    const float* __restrict__ ws, const float* __restrict__ wm,
    const float* __restrict__ wp, const float* __restrict__ mask,
    const int* __restrict__ rpe_index, const float* __restrict__ rpe_table)
{
    const int bid = blockIdx.x, tid = threadIdx.x;
    if (bid < 512) {
        int i = bid * 256 + tid;
        if (i < 49152) {
            ush h, l; split_hl(ws[i], h, l);
            ush* dst = g_ws3 + 3 * i;
            dst[0] = h; dst[1] = l; dst[2] = h;
        } else if (i < 98304) {
            ush h, l; split_hl(wm[i - 49152], h, l);
            ush* dst = g_wm3 + 3 * (i - 49152);
            dst[0] = h; dst[1] = l; dst[2] = h;
        } else {
            int ip = i - 98304;
            float v = wp[ip];
            __half hh = __float2half_rn(v);
            float r = v - __half2float(hh);
            __half hl = __float2half_rn(r);
            g_wp2[2 * ip] = *(ush*)&hh;
            g_wp2[2 * ip + 1] = *(ush*)&hl;
        }
        return;
    }
    if (bid < 8704) {
        size_t idx8 = (size_t)(bid - 512) * 256 + tid;
        size_t e0 = idx8 * 8;
        float4 xv0 = ((const float4*)x)[idx8 * 2];
        float4 xv1 = ((const float4*)x)[idx8 * 2 + 1];
        float xe[8] = {xv0.x, xv0.y, xv0.z, xv0.w, xv1.x, xv1.y, xv1.z, xv1.w};
        ush b0[24];
#pragma unroll
        for (int j = 0; j < 8; ++j) {
            ush h, l;
            split_hl(xe[j], h, l);
            b0[3 * j] = h; b0[3 * j + 1] = h; b0[3 * j + 2] = l;
        }
        uint4* d0 = (uint4*)(g_xs3 + 3 * e0);
        const uint4* s0 = (const uint4*)b0;
        d0[0] = s0[0]; d0[1] = s0[1]; d0[2] = s0[2];
        return;
    }
    if (bid < 17408) {
        const int q = tid >> 5, lane = tid & 31, g = lane >> 2, tg = lane & 3;
        const int il = (q >> 2) * 16 + ((q >> 1) & 1) * 8 + g;
        const int ml0 = (q & 1) * 16 + 2 * tg;
        if (bid < 16896) {
            int blin = bid - 8704;
            int w = blin >> 4, tile = blin & 15;
            int qt = tile >> 2, kt = tile & 3;
            int i = qt * 32 + il;
            int m0 = kt * 32 + ml0;
            const float* mrow = mask + (size_t)w * 16384 + i * 128;
            float2 mv01 = *(const float2*)(mrow + m0);
            float2 mv23 = *(const float2*)(mrow + m0 + 8);
            *(float4*)(g_maskf + ((size_t)w * 16 + tile) * 1024 + tid * 4) =
                make_float4(mv01.x, mv01.y, mv23.x, mv23.y);
            if (w == 0) {
                const int* irow = rpe_index + i * 128;
                int2 ix01 = *(const int2*)(irow + m0);
                int2 ix23 = *(const int2*)(irow + m0 + 8);
                float t0[8], t1[8], t2[8], t3[8];
                *(float4*)t0 = *(const float4*)(rpe_table + ix01.x * 8);
                *(float4*)(t0+4) = *(const float4*)(rpe_table + ix01.x * 8 + 4);
                *(float4*)t1 = *(const float4*)(rpe_table + ix01.y * 8);
                *(float4*)(t1+4) = *(const float4*)(rpe_table + ix01.y * 8 + 4);
                *(float4*)t2 = *(const float4*)(rpe_table + ix23.x * 8);
                *(float4*)(t2+4) = *(const float4*)(rpe_table + ix23.x * 8 + 4);
                *(float4*)t3 = *(const float4*)(rpe_table + ix23.y * 8);
                *(float4*)(t3+4) = *(const float4*)(rpe_table + ix23.y * 8 + 4);
#pragma unroll
                for (int h = 0; h < NHEADS; ++h)
                    *(float4*)(g_rpef + ((size_t)h * 16 + tile) * 1024 + tid * 4) =
                        make_float4(t0[h], t1[h], t2[h], t3[h]);
            }
            return;
        }
        {
            int w = bid - 16896;
            const float* mb = mask + (size_t)w * 16384;
#pragma unroll
            for (int tile = 0; tile < 4; ++tile) {
                int qt2 = tile >> 1, kt2 = tile & 1;
                int i = qt2 * 32 + il;
                int m0 = kt2 * 32 + ml0;
                float2 mv01 = *(const float2*)(mb + i * 128 + m0);
                float2 mv23 = *(const float2*)(mb + i * 128 + m0 + 8);
                *(float4*)(g_mmf + ((size_t)w * 4 + tile) * 1024 + tid * 4) =
                    make_float4(mv01.x, mv01.y, mv23.x, mv23.y);
            }
            return;
        }
    }
    {
        int j = (bid - 17408) * 256 + tid;          // 0..24575
        int t = j / 384, c = j % 384;
        const float* pr = pe + t * 128;
        const float* wr = wm + c * 128;
        float s = 0.f;
#pragma unroll 8
        for (int k = 0; k < 128; ++k) s += pr[k] * wr[k];
        g_peW[t * 384 + c] = s;
    }
}

// ---------------- mma / ldsm / cp.async macros ------------------------------
#define MMA_BF16(d, a, b0r, b1r) \
    asm volatile("mma.sync.aligned.m16n8k16.row.col.f32.bf16.bf16.f32 " \
        "{%0,%1,%2,%3},{%4,%5,%6,%7},{%8,%9},{%0,%1,%2,%3};" \
        : "+f"(d[0]), "+f"(d[1]), "+f"(d[2]), "+f"(d[3]) \
        : "r"(a[0]), "r"(a[1]), "r"(a[2]), "r"(a[3]), "r"(b0r), "r"(b1r))

#define MMA_F16(d, a, b0r, b1r) \
    asm volatile("mma.sync.aligned.m16n8k16.row.col.f32.f16.f16.f32 " \
        "{%0,%1,%2,%3},{%4,%5,%6,%7},{%8,%9},{%0,%1,%2,%3};" \
        : "+f"(d[0]), "+f"(d[1]), "+f"(d[2]), "+f"(d[3]) \
        : "r"(a[0]), "r"(a[1]), "r"(a[2]), "r"(a[3]), "r"(b0r), "r"(b1r))

#define LDSM4(r0, r1, r2, r3, addr) \
    asm volatile("ldmatrix.sync.aligned.m8n8.x4.shared.b16 {%0,%1,%2,%3}, [%4];" \
        : "=r"(r0), "=r"(r1), "=r"(r2), "=r"(r3) : "r"(addr))

#define CP16(dst, src) \
    asm volatile("cp.async.cg.shared.global [%0], [%1], 16;" :: "r"(dst), "l"(src))

#define CVT_F16X2(d, hi, lo) \
    asm("cvt.rn.f16x2.f32 %0, %1, %2;" : "=r"(d) : "f"(hi), "f"(lo))

#define PITCH 72
#define STAGE_ELEMS (128 * PITCH)
#define NSTAGE 3

// ---------------- generic GEMM mainloop as a macro body ----------------------
#define GEMM_MAIN(KTOT, MMAOP)                                                    \
    extern __shared__ __nv_bfloat16 smem[];                                       \
    __nv_bfloat16* As = smem;                                                     \
    __nv_bfloat16* Bs = smem + NSTAGE * STAGE_ELEMS;                              \
    const int tid = threadIdx.x;                                                  \
    const int lane = tid & 31, wid = tid >> 5;                                    \
    const int wm = (wid & 1) * 64, wn = (wid >> 1) * 32;                          \
    const int g = lane >> 2, tg = lane & 3;                                       \
    const size_t row0 = (size_t)blockIdx.y * 128;                                 \
    const int col0 = blockIdx.x * 128;                                            \
    constexpr int NC = (KTOT) / 64;                                               \
    const int ldr = tid >> 1;                                                     \
    const int ldu = (tid & 1) * 4;                                                \
    float acc[4][4][4] = {};                                                      \
    const int a_row = wm + (lane & 15);                                           \
    const int a_col = (lane >> 4) * 8;                                            \
    const int bq = lane >> 3;                                                     \
    const int b_row = wn + ((bq >> 1) * 8) + (lane & 7);                          \
    const int b_col = (bq & 1) * 8;                                               \
    LOAD_STAGE(0, 0, KTOT);                                                       \
    LOAD_STAGE(1, 1, KTOT);                                                       \
    _Pragma("unroll")                                                             \
    for (int kc = 0; kc < NC; ++kc) {                                             \
        const int cur = kc % NSTAGE;                                              \
        if (kc + 2 < NC) { asm volatile("cp.async.wait_group 1;"); }              \
        else             { asm volatile("cp.async.wait_group 0;"); }              \
        __syncthreads();                                                          \
        if (kc + 2 < NC) LOAD_STAGE(kc + 2, (kc + 2) % NSTAGE, KTOT);             \
        const __nv_bfloat16* Ad = As + cur * STAGE_ELEMS;                         \
        const __nv_bfloat16* Bd = Bs + cur * STAGE_ELEMS;                         \
        _Pragma("unroll")                                                         \
        for (int ks = 0; ks < 4; ++ks) {                                          \
            const int kb = ks * 16;                                               \
            uint32_t a[4][4], b[2][4];                                            \
            _Pragma("unroll")                                                     \
            for (int mt = 0; mt < 4; ++mt) {                                      \
                unsigned ad = (unsigned)__cvta_generic_to_shared(                 \
                    Ad + (a_row + mt * 16) * PITCH + kb + a_col);                 \
                LDSM4(a[mt][0], a[mt][1], a[mt][2], a[mt][3], ad);                \
            }                                                                     \
            _Pragma("unroll")                                                     \
            for (int p = 0; p < 2; ++p) {                                         \
                unsigned bd = (unsigned)__cvta_generic_to_shared(                 \
                    Bd + (b_row + p * 16) * PITCH + kb + b_col);                  \
                LDSM4(b[p][0], b[p][1], b[p][2], b[p][3], bd);                    \
            }                                                                     \
            _Pragma("unroll")                                                     \
            for (int mt = 0; mt < 4; ++mt)                                        \
                _Pragma("unroll")                                                 \
                for (int nt = 0; nt < 4; ++nt)                                    \
                    MMAOP(acc[mt][nt], a[mt], b[nt >> 1][(nt & 1) * 2],           \
                          b[nt >> 1][(nt & 1) * 2 + 1]);                          \
        }                                                                         \
        __syncthreads();                                                          \
    }

#define LOAD_STAGE(kc, s, KTOT)                                                  \
    {                                                                            \
        const __nv_bfloat16* Ab = A + (row0 + ldr) * (KTOT) + (kc) * 64;         \
        const __nv_bfloat16* Wb = W + (size_t)(col0 + ldr) * (KTOT) + (kc) * 64; \
        __nv_bfloat16* Ad = As + (s) * STAGE_ELEMS + ldr * PITCH;                \
        __nv_bfloat16* Bd = Bs + (s) * STAGE_ELEMS + ldr * PITCH;                \
        _Pragma("unroll")                                                        \
        for (int u = 0; u < 4; ++u) {                                            \
            unsigned da = (unsigned)__cvta_generic_to_shared(Ad + (ldu + u) * 8);\
            CP16(da, Ab + (ldu + u) * 8);                                        \
            unsigned db = (unsigned)__cvta_generic_to_shared(Bd + (ldu + u) * 8);\
            CP16(db, Wb + (ldu + u) * 8);                                        \
        }                                                                        \
        asm volatile("cp.async.commit_group;");                                  \
    }

// ---- QKV GEMM: epilogue writes attention-ready Q/K/V operands --------------
template<int MUT>
__global__ void __launch_bounds__(256) qkv_gemm(
    const __nv_bfloat16* __restrict__ A, const __nv_bfloat16* __restrict__ W,
    ush* __restrict__ q3, ush* __restrict__ k3, ush* __restrict__ vt)
{
    GEMM_MAIN(384, MMA_BF16)

    const int b = blockIdx.y;
#pragma unroll
    for (int mt = 0; mt < 4; ++mt) {
#pragma unroll
        for (int nt = 0; nt < 4; ++nt) {
            const int c = wn + nt * 8 + 2 * tg;
            const int hh = c >> 4, d = c & 15;
            const int r = wm + mt * 16 + g;
            float v0 = acc[mt][nt][0], v1 = acc[mt][nt][1];
            float v2 = acc[mt][nt][2], v3 = acc[mt][nt][3];
            if (MUT) {
                const float* pw  = g_peW + (r & 63) * 384 + col0 + c;
                const float* pw8 = g_peW + ((r + 8) & 63) * 384 + col0 + c;
                v0 += pw[0];  v1 += pw[1];
                v2 += pw8[0]; v3 += pw8[1];
            }
            if (col0 == 0) {                           // Q: A-side triplets x0.25
                unsigned tb[3];
                size_t o = ((size_t)(b * 8 + hh) * 128 + r) * 48 + 3 * d;
                trip2(v0 * 0.25f, v1 * 0.25f, tb);
                ((unsigned*)(q3 + o))[0] = tb[0];
                ((unsigned*)(q3 + o))[1] = tb[1];
                ((unsigned*)(q3 + o))[2] = tb[2];
                trip2(v2 * 0.25f, v3 * 0.25f, tb);
                ((unsigned*)(q3 + o + 48 * 8))[0] = tb[0];
                ((unsigned*)(q3 + o + 48 * 8))[1] = tb[1];
                ((unsigned*)(q3 + o + 48 * 8))[2] = tb[2];
            } else if (col0 == 128) {                  // K: B-side triplets
                unsigned tb[3];
                size_t o = ((size_t)(b * 8 + hh) * 128 + r) * 48 + 3 * d;
                trip2B(v0, v1, tb);
                ((unsigned*)(k3 + o))[0] = tb[0];
                ((unsigned*)(k3 + o))[1] = tb[1];
                ((unsigned*)(k3 + o))[2] = tb[2];
                trip2B(v2, v3, tb);
                ((unsigned*)(k3 + o + 48 * 8))[0] = tb[0];
                ((unsigned*)(k3 + o + 48 * 8))[1] = tb[1];
                ((unsigned*)(k3 + o + 48 * 8))[2] = tb[2];
            } else {                                   // V: fp16 transposed [d][m]
                ush* vb = vt + (size_t)(b * 8 + hh) * 16 * 128;
                __half h0 = __float2half_rn(v0);
                __half h1 = __float2half_rn(v1);
                __half h2 = __float2half_rn(v2);
                __half h3 = __float2half_rn(v3);
                vb[d * 128 + r]           = *(ush*)&h0;
                vb[(d + 1) * 128 + r]     = *(ush*)&h1;
                vb[d * 128 + r + 8]       = *(ush*)&h2;
                vb[(d + 1) * 128 + r + 8] = *(ush*)&h3;
            }
        }
    }
}

// ---- projection GEMM: fp16 A (duplicated pairs) x fp16 (h,l) weights -------
__global__ void __launch_bounds__(256) proj_gemm(
    const __nv_bfloat16* __restrict__ A, const __nv_bfloat16* __restrict__ W,
    const float* __restrict__ bvec, float* __restrict__ C)
{
    GEMM_MAIN(512, MMA_F16)
#pragma unroll
    for (int mt = 0; mt < 4; ++mt) {
#pragma unroll
        for (int nt = 0; nt < 4; ++nt) {
            size_t row = row0 + wm + mt * 16 + g;
            int col = col0 + wn + nt * 8 + 2 * tg;
            float b0 = bvec[col], b1 = bvec[col + 1];
            *(float2*)&C[row * 128 + col] =
                make_float2(acc[mt][nt][0] + b0, acc[mt][nt][1] + b1);
            *(float2*)&C[(row + 8) * 128 + col] =
                make_float2(acc[mt][nt][2] + b0, acc[mt][nt][3] + b1);
        }
    }
}

// ---------------- tensor-core attention --------------------------------------
#define PQ 56
#define PVH 136
#define ATTN_SMEM ((2 * 128 * PQ + 16 * PVH) * 2)

__global__ void __launch_bounds__(128) attn_tc()
{
    extern __shared__ __nv_bfloat16 sm[];
    __nv_bfloat16* Qs = sm;
    __nv_bfloat16* Ks = sm + 128 * PQ;
    ush* VtH = (ush*)(sm + 2 * 128 * PQ);

    const int b = blockIdx.x;
    const bool self = blockIdx.y < 8;
    const int h = self ? blockIdx.y : blockIdx.y - 8;
    const int tid = threadIdx.x, lane = tid & 31, wid = tid >> 5;

    const ush* q3 = (self ? g_q3s : g_q3m) + (size_t)(b * 8 + h) * 128 * 48;
    const ush* k3 = (self ? g_k3s : g_k3m) + (size_t)(b * 8 + h) * 128 * 48;
    const ush* vt = (self ? g_vts : g_vtm) + (size_t)(b * 8 + h) * 16 * 128;

    // ---- coalesced cp.async staging ----
    {
        const int qsrc = self ? tid : ((tid < 64) ? 64 + tid : tid - 64);
#pragma unroll
        for (int u = 0; u < 6; ++u) {
            unsigned dq = (unsigned)__cvta_generic_to_shared(Qs + tid * PQ + u * 8);
            CP16(dq, q3 + qsrc * 48 + u * 8);
            unsigned dk = (unsigned)__cvta_generic_to_shared(Ks + tid * PQ + u * 8);
            CP16(dk, k3 + tid * 48 + u * 8);
        }
#pragma unroll
        for (int u = 0; u < 2; ++u) {
            int ch = tid + u * 128;
            unsigned dv = (unsigned)__cvta_generic_to_shared(
                VtH + (ch >> 4) * PVH + (ch & 15) * 8);
            CP16(dv, vt + (ch >> 4) * 128 + (ch & 15) * 8);
        }
        asm volatile("cp.async.commit_group;");
        asm volatile("cp.async.wait_group 0;");
    }
    __syncthreads();

    const int g = lane >> 2, tg = lane & 3;
    const int r0 = wid * 32;
    const int a_row = lane & 15, a_col = (lane >> 4) * 8;
    const int bq = lane >> 3;
    const int b_rsub = ((bq >> 1) * 8) + (lane & 7);
    const int b_col8 = (bq & 1) * 8;

    const int nchunk = self ? 4 : 2;
    const int kb0 = (self || wid < 2) ? 0 : 64;
    const float4* mask_t = self
        ? (const float4*)(g_maskf + ((size_t)(b & 511) * 16 + wid * 4) * 1024)
        : (const float4*)(g_mmf + ((size_t)(b & 511) * 4 + (wid & 1) * 2) * 1024);
    const float4* rpe_t = (const float4*)(g_rpef + ((size_t)h * 16 + wid * 4) * 1024);

    uint32_t aq[3][2][4];
#pragma unroll
    for (int kt = 0; kt < 3; ++kt)
#pragma unroll
        for (int mt = 0; mt < 2; ++mt) {
            unsigned ad = (unsigned)__cvta_generic_to_shared(
                Qs + (r0 + mt * 16 + a_row) * PQ + kt * 16 + a_col);
            LDSM4(aq[kt][mt][0], aq[kt][mt][1], aq[kt][mt][2], aq[kt][mt][3], ad);
        }

    float accO[2][2][4] = {};
    float rs[4] = {0.f, 0.f, 0.f, 0.f};

    for (int mc = 0; mc < nchunk; ++mc) {
        const int key0 = kb0 + mc * 32;
        float4 f[8];
        {
            const float4* mt4 = mask_t + (size_t)mc * 256;
#pragma unroll
            for (int q = 0; q < 8; ++q) f[q] = mt4[q * 32 + lane];
            if (self) {
                const float4* rt4 = rpe_t + (size_t)mc * 256;
#pragma unroll
                for (int q = 0; q < 8; ++q) {
                    float4 r = rt4[q * 32 + lane];
                    f[q].x += r.x; f[q].y += r.y; f[q].z += r.z; f[q].w += r.w;
                }
            }
        }

        float accS[2][4][4] = {};
#pragma unroll
        for (int kt = 0; kt < 3; ++kt) {
            uint32_t bf[2][4];
#pragma unroll
            for (int p = 0; p < 2; ++p) {
                unsigned bd = (unsigned)__cvta_generic_to_shared(
                    Ks + (key0 + p * 16 + b_rsub) * PQ + kt * 16 + b_col8);
                LDSM4(bf[p][0], bf[p][1], bf[p][2], bf[p][3], bd);
            }
#pragma unroll
            for (int mt = 0; mt < 2; ++mt)
#pragma unroll
                for (int nt = 0; nt < 4; ++nt)
                    MMA_BF16(accS[mt][nt], aq[kt][mt], bf[nt >> 1][(nt & 1) * 2],
                             bf[nt >> 1][(nt & 1) * 2 + 1]);
        }
#pragma unroll
        for (int mt = 0; mt < 2; ++mt) {
#pragma unroll
            for (int nt = 0; nt < 4; ++nt) {
                const float* f0 = (const float*)&f[mt * 4 + (nt >> 1)];
                const float* f1 = (const float*)&f[mt * 4 + 2 + (nt >> 1)];
                const int e0 = (nt & 1) * 2;
                float p0 = __expf(accS[mt][nt][0] + f0[e0]);
                float p1 = __expf(accS[mt][nt][1] + f0[e0 + 1]);
                float p2 = __expf(accS[mt][nt][2] + f1[e0]);
                float p3 = __expf(accS[mt][nt][3] + f1[e0 + 1]);
                rs[2 * mt]     += p0 + p1;
                rs[2 * mt + 1] += p2 + p3;
                accS[mt][nt][0] = p0; accS[mt][nt][1] = p1;
                accS[mt][nt][2] = p2; accS[mt][nt][3] = p3;
            }
        }
#pragma unroll
        for (int kt2 = 0; kt2 < 2; ++kt2) {
            uint32_t a2[2][4];
#pragma unroll
            for (int mt = 0; mt < 2; ++mt) {
                CVT_F16X2(a2[mt][0], accS[mt][2 * kt2][1],     accS[mt][2 * kt2][0]);
                CVT_F16X2(a2[mt][1], accS[mt][2 * kt2][3],     accS[mt][2 * kt2][2]);
                CVT_F16X2(a2[mt][2], accS[mt][2 * kt2 + 1][1], accS[mt][2 * kt2 + 1][0]);
                CVT_F16X2(a2[mt][3], accS[mt][2 * kt2 + 1][3], accS[mt][2 * kt2 + 1][2]);
            }
            uint32_t b2[4];
            unsigned bd = (unsigned)__cvta_generic_to_shared(
                VtH + b_rsub * PVH + key0 + kt2 * 16 + b_col8);
            LDSM4(b2[0], b2[1], b2[2], b2[3], bd);
#pragma unroll
            for (int mt = 0; mt < 2; ++mt) {
                MMA_F16(accO[mt][0], a2[mt], b2[0], b2[1]);
                MMA_F16(accO[mt][1], a2[mt], b2[2], b2[3]);
            }
        }
    }

#pragma unroll
    for (int s = 0; s < 4; ++s) {
        rs[s] += __shfl_xor_sync(0xffffffffu, rs[s], 1);
        rs[s] += __shfl_xor_sync(0xffffffffu, rs[s], 2);
    }
    float inv[4];
#pragma unroll
    for (int s = 0; s < 4; ++s) inv[s] = 1.f / rs[s];

    // ---- write O as duplicated fp16 pairs into concat (K'-major) ----
    const int cb2 = self ? 256 : 0;      // self occupies cols 128..255 -> K' 256..511
#pragma unroll
    for (int mt = 0; mt < 2; ++mt) {
#pragma unroll
        for (int nt2 = 0; nt2 < 2; ++nt2) {
            const int d0 = nt2 * 8 + 2 * tg;
            const int rA = r0 + mt * 16 + g;
            unsigned* oA = (unsigned*)(g_concat2h +
                ((size_t)b * NTOK + rA) * 512 + cb2 + 2 * (h * HD + d0));
            oA[0] = dup_h(accO[mt][nt2][0] * inv[2 * mt]);
            oA[1] = dup_h(accO[mt][nt2][1] * inv[2 * mt]);
            unsigned* oB = (unsigned*)(g_concat2h +
                ((size_t)b * NTOK + rA + 8) * 512 + cb2 + 2 * (h * HD + d0));
            oB[0] = dup_h(accO[mt][nt2][2] * inv[2 * mt + 1]);
            oB[1] = dup_h(accO[mt][nt2][3] * inv[2 * mt + 1]);
        }
    }
}

// ---------------- launch ----------------------------------------------------
extern "C" void kernel_launch(void* const* d_in, const int* in_sizes, int n_in,
                              void* d_out, int out_size)
{
    const float* x         = (const float*)d_in[0];
    const float* mask      = (const float*)d_in[1];
    const float* w_self    = (const float*)d_in[2];
    const float* w_mut     = (const float*)d_in[3];
    const float* w_proj    = (const float*)d_in[4];
    const float* b_proj    = (const float*)d_in[5];
    const float* rpe_table = (const float*)d_in[6];
    const float* pe        = (const float*)d_in[7];
    const int*   rpe_index = (const int*)d_in[8];
    float* out = (float*)d_out;

    ush *xs, *cc, *ws, *wm, *wp;
    ush *q3s, *k3s, *vts, *q3m, *k3m, *vtm;
    cudaGetSymbolAddress((void**)&ws, g_ws3);
    cudaGetSymbolAddress((void**)&wm, g_wm3);
    cudaGetSymbolAddress((void**)&wp, g_wp2);
    cudaGetSymbolAddress((void**)&xs, g_xs3);
    cudaGetSymbolAddress((void**)&cc, g_concat2h);
    cudaGetSymbolAddress((void**)&q3s, g_q3s);
    cudaGetSymbolAddress((void**)&k3s, g_k3s);
    cudaGetSymbolAddress((void**)&vts, g_vts);
    cudaGetSymbolAddress((void**)&q3m, g_q3m);
    cudaGetSymbolAddress((void**)&k3m, g_k3m);
    cudaGetSymbolAddress((void**)&vtm, g_vtm);

    const int SMEM = 2 * NSTAGE * STAGE_ELEMS * (int)sizeof(__nv_bfloat16); // 110592
    cudaFuncSetAttribute(qkv_gemm<0>, cudaFuncAttributeMaxDynamicSharedMemorySize, SMEM);
    cudaFuncSetAttribute(qkv_gemm<1>, cudaFuncAttributeMaxDynamicSharedMemorySize, SMEM);
    cudaFuncSetAttribute(proj_gemm, cudaFuncAttributeMaxDynamicSharedMemorySize, SMEM);
    cudaFuncSetAttribute(attn_tc, cudaFuncAttributeMaxDynamicSharedMemorySize, ATTN_SMEM);

    // launch 1: all prep
    prep_all<<<17504, 256>>>(x, pe, w_self, w_mut, w_proj, mask, rpe_index, rpe_table);

    // launches 2,3: QKV GEMMs (shared x-split; mut adds peW in epilogue)
    qkv_gemm<0><<<dim3(3, 1024), 256, SMEM>>>(
        (const __nv_bfloat16*)xs, (const __nv_bfloat16*)ws, q3s, k3s, vts);
    qkv_gemm<1><<<dim3(3, 1024), 256, SMEM>>>(
        (const __nv_bfloat16*)xs, (const __nv_bfloat16*)wm, q3m, k3m, vtm);

    // launch 4: tensor-core attention  (<- ncu capture slot)
    attn_tc<<<dim3(WB, 16), 128, ATTN_SMEM>>>();

    // launch 5: projection (K' = 512, fp16)
    proj_gemm<<<dim3(1, 1024), 256, SMEM>>>(
        (const __nv_bfloat16*)cc, (const __nv_bfloat16*)wp, b_proj, out);
}

// round 16
// speedup vs baseline: 1.5999x; 1.0074x over previous
#include <cuda_runtime.h>
#include <cuda_bf16.h>
#include <cuda_fp16.h>
#include <cstddef>
#include <cstdint>

#define WB     1024
#define NTOK   128
#define NHEADS 8
#define HD     16
#define MROWS  (WB * NTOK)          // 131072

typedef unsigned long long ull;
typedef unsigned short ush;

// ---------------- scratch (device globals; no runtime allocation) ----------
__device__ ush g_xs3 [(size_t)MROWS * 384];             // x split (A-side), shared
__device__ ush g_ws3 [384 * 384];
__device__ ush g_wm3 [384 * 384];
__device__ ush g_wp2 [128 * 512];                       // w_proj fp16 (h,l) pairs
__device__ float g_peW[64 * 384];                       // pe @ w_mut^T
__device__ ush g_q3s[(size_t)WB * NHEADS * NTOK * 48];
__device__ ush g_k3s[(size_t)WB * NHEADS * NTOK * 48];
__device__ ush g_vts[(size_t)WB * NHEADS * HD * NTOK];
__device__ ush g_q3m[(size_t)WB * NHEADS * NTOK * 48];
__device__ ush g_k3m[(size_t)WB * NHEADS * NTOK * 48];
__device__ ush g_vtm[(size_t)WB * NHEADS * HD * NTOK];
__device__ ush g_concat2h[(size_t)MROWS * 512];         // fp16 (c,c) pairs, K'=512
__device__ float g_maskf[(size_t)512 * 16 * 1024];
__device__ float g_rpef [(size_t)NHEADS * 16 * 1024];
__device__ float g_mmf  [(size_t)512 * 4 * 1024];

__device__ __forceinline__ void split_hl(float v, ush& h, ush& l) {
    __nv_bfloat16 hh = __float2bfloat16(v);
    float r = v - __bfloat162float(hh);
    __nv_bfloat16 ll = __float2bfloat16(r);
    h = *(ush*)&hh;
    l = *(ush*)&ll;
}

__device__ __forceinline__ void trip2(float a, float b, unsigned* o) {
    ush h0, l0, h1, l1;
    split_hl(a, h0, l0); split_hl(b, h1, l1);
    o[0] = (unsigned)h0 | ((unsigned)h0 << 16);
    o[1] = (unsigned)l0 | ((unsigned)h1 << 16);
    o[2] = (unsigned)h1 | ((unsigned)l1 << 16);
}
__device__ __forceinline__ void trip2B(float a, float b, unsigned* o) {
    ush h0, l0, h1, l1;
    split_hl(a, h0, l0); split_hl(b, h1, l1);
    o[0] = (unsigned)h0 | ((unsigned)l0 << 16);
    o[1] = (unsigned)h0 | ((unsigned)h1 << 16);
    o[2] = (unsigned)l1 | ((unsigned)h1 << 16);
}
__device__ __forceinline__ unsigned dup_h(float v) {
    __half hv = __float2half_rn(v);
    unsigned u = *(ush*)&hv;
    return u | (u << 16);
}

// ---------------- fused prep (ONE launch) -----------------------------------
__global__ void __launch_bounds__(256) prep_all(
    const float* __restrict__ x, const float* __restrict__ pe,
    const float* __restrict__ ws, const float* __restrict__ wm,
    const float* __restrict__ wp, const float* __restrict__ mask,
    const int* __restrict__ rpe_index, const float* __restrict__ rpe_table)
{
    const int bid = blockIdx.x, tid = threadIdx.x;
    if (bid < 512) {
        int i = bid * 256 + tid;
        if (i < 49152) {
            ush h, l; split_hl(ws[i], h, l);
            ush* dst = g_ws3 + 3 * i;
            dst[0] = h; dst[1] = l; dst[2] = h;
        } else if (i < 98304) {
            ush h, l; split_hl(wm[i - 49152], h, l);
            ush* dst = g_wm3 + 3 * (i - 49152);
            dst[0] = h; dst[1] = l; dst[2] = h;
        } else {
            int ip = i - 98304;
            float v = wp[ip];
            __half hh = __float2half_rn(v);
            float r = v - __half2float(hh);
            __half hl = __float2half_rn(r);
            g_wp2[2 * ip] = *(ush*)&hh;
            g_wp2[2 * ip + 1] = *(ush*)&hl;
        }
        return;
    }
    if (bid < 8704) {
        size_t idx8 = (size_t)(bid - 512) * 256 + tid;
        size_t e0 = idx8 * 8;
        float4 xv0 = ((const float4*)x)[idx8 * 2];
        float4 xv1 = ((const float4*)x)[idx8 * 2 + 1];
        float xe[8] = {xv0.x, xv0.y, xv0.z, xv0.w, xv1.x, xv1.y, xv1.z, xv1.w};
        ush b0[24];
#pragma unroll
        for (int j = 0; j < 8; ++j) {
            ush h, l;
            split_hl(xe[j], h, l);
            b0[3 * j] = h; b0[3 * j + 1] = h; b0[3 * j + 2] = l;
        }
        uint4* d0 = (uint4*)(g_xs3 + 3 * e0);
        const uint4* s0 = (const uint4*)b0;
        d0[0] = s0[0]; d0[1] = s0[1]; d0[2] = s0[2];
        return;
    }
    if (bid < 17408) {
        const int q = tid >> 5, lane = tid & 31, g = lane >> 2, tg = lane & 3;
        const int il = (q >> 2) * 16 + ((q >> 1) & 1) * 8 + g;
        const int ml0 = (q & 1) * 16 + 2 * tg;
        if (bid < 16896) {
            int blin = bid - 8704;
            int w = blin >> 4, tile = blin & 15;
            int qt = tile >> 2, kt = tile & 3;
            int i = qt * 32 + il;
            int m0 = kt * 32 + ml0;
            const float* mrow = mask + (size_t)w * 16384 + i * 128;
            float2 mv01 = *(const float2*)(mrow + m0);
            float2 mv23 = *(const float2*)(mrow + m0 + 8);
            *(float4*)(g_maskf + ((size_t)w * 16 + tile) * 1024 + tid * 4) =
                make_float4(mv01.x, mv01.y, mv23.x, mv23.y);
            if (w == 0) {
                const int* irow = rpe_index + i * 128;
                int2 ix01 = *(const int2*)(irow + m0);
                int2 ix23 = *(const int2*)(irow + m0 + 8);
                float t0[8], t1[8], t2[8], t3[8];
                *(float4*)t0 = *(const float4*)(rpe_table + ix01.x * 8);
                *(float4*)(t0+4) = *(const float4*)(rpe_table + ix01.x * 8 + 4);
                *(float4*)t1 = *(const float4*)(rpe_table + ix01.y * 8);
                *(float4*)(t1+4) = *(const float4*)(rpe_table + ix01.y * 8 + 4);
                *(float4*)t2 = *(const float4*)(rpe_table + ix23.x * 8);
                *(float4*)(t2+4) = *(const float4*)(rpe_table + ix23.x * 8 + 4);
                *(float4*)t3 = *(const float4*)(rpe_table + ix23.y * 8);
                *(float4*)(t3+4) = *(const float4*)(rpe_table + ix23.y * 8 + 4);
#pragma unroll
                for (int h = 0; h < NHEADS; ++h)
                    *(float4*)(g_rpef + ((size_t)h * 16 + tile) * 1024 + tid * 4) =
                        make_float4(t0[h], t1[h], t2[h], t3[h]);
            }
            return;
        }
        {
            int w = bid - 16896;
            const float* mb = mask + (size_t)w * 16384;
#pragma unroll
            for (int tile = 0; tile < 4; ++tile) {
                int qt2 = tile >> 1, kt2 = tile & 1;
                int i = qt2 * 32 + il;
                int m0 = kt2 * 32 + ml0;
                float2 mv01 = *(const float2*)(mb + i * 128 + m0);
                float2 mv23 = *(const float2*)(mb + i * 128 + m0 + 8);
                *(float4*)(g_mmf + ((size_t)w * 4 + tile) * 1024 + tid * 4) =
                    make_float4(mv01.x, mv01.y, mv23.x, mv23.y);
            }
            return;
        }
    }
    {
        int j = (bid - 17408) * 256 + tid;
        int t = j / 384, c = j % 384;
        const float* pr = pe + t * 128;
        const float* wr = wm + c * 128;
        float s = 0.f;
#pragma unroll 8
        for (int k = 0; k < 128; ++k) s += pr[k] * wr[k];
        g_peW[t * 384 + c] = s;
    }
}

// ---------------- mma / ldsm / cp.async macros ------------------------------
#define MMA_BF16(d, a, b0r, b1r) \
    asm volatile("mma.sync.aligned.m16n8k16.row.col.f32.bf16.bf16.f32 " \
        "{%0,%1,%2,%3},{%4,%5,%6,%7},{%8,%9},{%0,%1,%2,%3};" \
        : "+f"(d[0]), "+f"(d[1]), "+f"(d[2]), "+f"(d[3]) \
        : "r"(a[0]), "r"(a[1]), "r"(a[2]), "r"(a[3]), "r"(b0r), "r"(b1r))

#define MMA_F16(d, a, b0r, b1r) \
    asm volatile("mma.sync.aligned.m16n8k16.row.col.f32.f16.f16.f32 " \
        "{%0,%1,%2,%3},{%4,%5,%6,%7},{%8,%9},{%0,%1,%2,%3};" \
        : "+f"(d[0]), "+f"(d[1]), "+f"(d[2]), "+f"(d[3]) \
        : "r"(a[0]), "r"(a[1]), "r"(a[2]), "r"(a[3]), "r"(b0r), "r"(b1r))

#define LDSM4(r0, r1, r2, r3, addr) \
    asm volatile("ldmatrix.sync.aligned.m8n8.x4.shared.b16 {%0,%1,%2,%3}, [%4];" \
        : "=r"(r0), "=r"(r1), "=r"(r2), "=r"(r3) : "r"(addr))

#define CP16(dst, src) \
    asm volatile("cp.async.cg.shared.global [%0], [%1], 16;" :: "r"(dst), "l"(src))

#define CVT_F16X2(d, hi, lo) \
    asm("cvt.rn.f16x2.f32 %0, %1, %2;" : "=r"(d) : "f"(hi), "f"(lo))

#define PITCH 72
#define STAGE_ELEMS (128 * PITCH)
#define NSTAGE 3

// ---------------- generic GEMM mainloop (col index = CI) ---------------------
#define GEMM_MAIN(KTOT, MMAOP, CI)                                                \
    extern __shared__ __nv_bfloat16 smem[];                                       \
    __nv_bfloat16* As = smem;                                                     \
    __nv_bfloat16* Bs = smem + NSTAGE * STAGE_ELEMS;                              \
    const int tid = threadIdx.x;                                                  \
    const int lane = tid & 31, wid = tid >> 5;                                    \
    const int wm = (wid & 1) * 64, wn = (wid >> 1) * 32;                          \
    const int g = lane >> 2, tg = lane & 3;                                       \
    const size_t row0 = (size_t)blockIdx.y * 128;                                 \
    const int col0 = (CI) * 128;                                                  \
    constexpr int NC = (KTOT) / 64;                                               \
    const int ldr = tid >> 1;                                                     \
    const int ldu = (tid & 1) * 4;                                                \
    float acc[4][4][4] = {};                                                      \
    const int a_row = wm + (lane & 15);                                           \
    const int a_col = (lane >> 4) * 8;                                            \
    const int bq = lane >> 3;                                                     \
    const int b_row = wn + ((bq >> 1) * 8) + (lane & 7);                          \
    const int b_col = (bq & 1) * 8;                                               \
    LOAD_STAGE(0, 0, KTOT);                                                       \
    LOAD_STAGE(1, 1, KTOT);                                                       \
    _Pragma("unroll")                                                             \
    for (int kc = 0; kc < NC; ++kc) {                                             \
        const int cur = kc % NSTAGE;                                              \
        if (kc + 2 < NC) { asm volatile("cp.async.wait_group 1;"); }              \
        else             { asm volatile("cp.async.wait_group 0;"); }              \
        __syncthreads();                                                          \
        if (kc + 2 < NC) LOAD_STAGE(kc + 2, (kc + 2) % NSTAGE, KTOT);             \
        const __nv_bfloat16* Ad = As + cur * STAGE_ELEMS;                         \
        const __nv_bfloat16* Bd = Bs + cur * STAGE_ELEMS;                         \
        _Pragma("unroll")                                                         \
        for (int ks = 0; ks < 4; ++ks) {                                          \
            const int kb = ks * 16;                                               \
            uint32_t a[4][4], b[2][4];                                            \
            _Pragma("unroll")                                                     \
            for (int mt = 0; mt < 4; ++mt) {                                      \
                unsigned ad = (unsigned)__cvta_generic_to_shared(                 \
                    Ad + (a_row + mt * 16) * PITCH + kb + a_col);                 \
                LDSM4(a[mt][0], a[mt][1], a[mt][2], a[mt][3], ad);                \
            }                                                                     \
            _Pragma("unroll")                                                     \
            for (int p = 0; p < 2; ++p) {                                         \
                unsigned bd = (unsigned)__cvta_generic_to_shared(                 \
                    Bd + (b_row + p * 16) * PITCH + kb + b_col);                  \
                LDSM4(b[p][0], b[p][1], b[p][2], b[p][3], bd);                    \
            }                                                                     \
            _Pragma("unroll")                                                     \
            for (int mt = 0; mt < 4; ++mt)                                        \
                _Pragma("unroll")                                                 \
                for (int nt = 0; nt < 4; ++nt)                                    \
                    MMAOP(acc[mt][nt], a[mt], b[nt >> 1][(nt & 1) * 2],           \
                          b[nt >> 1][(nt & 1) * 2 + 1]);                          \
        }                                                                         \
        __syncthreads();                                                          \
    }

#define LOAD_STAGE(kc, s, KTOT)                                                  \
    {                                                                            \
        const __nv_bfloat16* Ab = A + (row0 + ldr) * (KTOT) + (kc) * 64;         \
        const __nv_bfloat16* Wb = W + (size_t)(col0 + ldr) * (KTOT) + (kc) * 64; \
        __nv_bfloat16* Ad = As + (s) * STAGE_ELEMS + ldr * PITCH;                \
        __nv_bfloat16* Bd = Bs + (s) * STAGE_ELEMS + ldr * PITCH;                \
        _Pragma("unroll")                                                        \
        for (int u = 0; u < 4; ++u) {                                            \
            unsigned da = (unsigned)__cvta_generic_to_shared(Ad + (ldu + u) * 8);\
            CP16(da, Ab + (ldu + u) * 8);                                        \
            unsigned db = (unsigned)__cvta_generic_to_shared(Bd + (ldu + u) * 8);\
            CP16(db, Wb + (ldu + u) * 8);                                        \
        }                                                                        \
        asm volatile("cp.async.commit_group;");                                  \
    }

// ---- merged QKV GEMM: grid.x 0..2 = self Q/K/V, 3..5 = mut Q/K/V ------------
__global__ void __launch_bounds__(256) qkv_all()
{
    const bool mut = blockIdx.x >= 3;
    const __nv_bfloat16* A = (const __nv_bfloat16*)g_xs3;
    const __nv_bfloat16* W = (const __nv_bfloat16*)(mut ? g_wm3 : g_ws3);
    ush* q3 = mut ? g_q3m : g_q3s;
    ush* k3 = mut ? g_k3m : g_k3s;
    ush* vt = mut ? g_vtm : g_vts;

    GEMM_MAIN(384, MMA_BF16, (blockIdx.x >= 3 ? blockIdx.x - 3 : blockIdx.x))

    const int b = blockIdx.y;
#pragma unroll
    for (int mt = 0; mt < 4; ++mt) {
#pragma unroll
        for (int nt = 0; nt < 4; ++nt) {
            const int c = wn + nt * 8 + 2 * tg;
            const int hh = c >> 4, d = c & 15;
            const int r = wm + mt * 16 + g;
            float v0 = acc[mt][nt][0], v1 = acc[mt][nt][1];
            float v2 = acc[mt][nt][2], v3 = acc[mt][nt][3];
            if (mut) {
                const float* pw  = g_peW + (r & 63) * 384 + col0 + c;
                const float* pw8 = g_peW + ((r + 8) & 63) * 384 + col0 + c;
                v0 += pw[0];  v1 += pw[1];
                v2 += pw8[0]; v3 += pw8[1];
            }
            if (col0 == 0) {
                unsigned tb[3];
                size_t o = ((size_t)(b * 8 + hh) * 128 + r) * 48 + 3 * d;
                trip2(v0 * 0.25f, v1 * 0.25f, tb);
                ((unsigned*)(q3 + o))[0] = tb[0];
                ((unsigned*)(q3 + o))[1] = tb[1];
                ((unsigned*)(q3 + o))[2] = tb[2];
                trip2(v2 * 0.25f, v3 * 0.25f, tb);
                ((unsigned*)(q3 + o + 48 * 8))[0] = tb[0];
                ((unsigned*)(q3 + o + 48 * 8))[1] = tb[1];
                ((unsigned*)(q3 + o + 48 * 8))[2] = tb[2];
            } else if (col0 == 128) {
                unsigned tb[3];
                size_t o = ((size_t)(b * 8 + hh) * 128 + r) * 48 + 3 * d;
                trip2B(v0, v1, tb);
                ((unsigned*)(k3 + o))[0] = tb[0];
                ((unsigned*)(k3 + o))[1] = tb[1];
                ((unsigned*)(k3 + o))[2] = tb[2];
                trip2B(v2, v3, tb);
                ((unsigned*)(k3 + o + 48 * 8))[0] = tb[0];
                ((unsigned*)(k3 + o + 48 * 8))[1] = tb[1];
                ((unsigned*)(k3 + o + 48 * 8))[2] = tb[2];
            } else {
                ush* vb = vt + (size_t)(b * 8 + hh) * 16 * 128;
                __half h0 = __float2half_rn(v0);
                __half h1 = __float2half_rn(v1);
                __half h2 = __float2half_rn(v2);
                __half h3 = __float2half_rn(v3);
                vb[d * 128 + r]           = *(ush*)&h0;
                vb[(d + 1) * 128 + r]     = *(ush*)&h1;
                vb[d * 128 + r + 8]       = *(ush*)&h2;
                vb[(d + 1) * 128 + r + 8] = *(ush*)&h3;
            }
        }
    }
}

// ---- projection GEMM: fp16 A (duplicated pairs) x fp16 (h,l) weights -------
__global__ void __launch_bounds__(256) proj_gemm(
    const __nv_bfloat16* __restrict__ A, const __nv_bfloat16* __restrict__ W,
    const float* __restrict__ bvec, float* __restrict__ C)
{
    GEMM_MAIN(512, MMA_F16, blockIdx.x)
#pragma unroll
    for (int mt = 0; mt < 4; ++mt) {
#pragma unroll
        for (int nt = 0; nt < 4; ++nt) {
            size_t row = row0 + wm + mt * 16 + g;
            int col = col0 + wn + nt * 8 + 2 * tg;
            float b0 = bvec[col], b1 = bvec[col + 1];
            *(float2*)&C[row * 128 + col] =
                make_float2(acc[mt][nt][0] + b0, acc[mt][nt][1] + b1);
            *(float2*)&C[(row + 8) * 128 + col] =
                make_float2(acc[mt][nt][2] + b0, acc[mt][nt][3] + b1);
        }
    }
}

// ---------------- tensor-core attention: 2 heads per block -------------------
// grid (WB, 8): y<4 self pair (2y, 2y+1); y>=4 mut pair.
#define PQ 56
#define PVH 136
#define HP_Q (128 * PQ)
#define HP_V (16 * PVH)
#define ATTN_SMEM ((4 * HP_Q + 2 * HP_V) * 2)

__global__ void __launch_bounds__(128) attn_tc()
{
    extern __shared__ __nv_bfloat16 sm[];
    // layout: Qs0, Qs1, Ks0, Ks1, Vt0, Vt1
    const int b = blockIdx.x;
    const bool self = blockIdx.y < 4;
    const int h0 = self ? 2 * blockIdx.y : 2 * (blockIdx.y - 4);
    const int tid = threadIdx.x, lane = tid & 31, wid = tid >> 5;

    // ---- coalesced cp.async staging for both heads ----
    {
        const int qsrc = self ? tid : ((tid < 64) ? 64 + tid : tid - 64);
#pragma unroll
        for (int hp = 0; hp < 2; ++hp) {
            const ush* q3 = (self ? g_q3s : g_q3m) + (size_t)(b * 8 + h0 + hp) * 128 * 48;
            const ush* k3 = (self ? g_k3s : g_k3m) + (size_t)(b * 8 + h0 + hp) * 128 * 48;
            const ush* vt = (self ? g_vts : g_vtm) + (size_t)(b * 8 + h0 + hp) * 16 * 128;
            __nv_bfloat16* Qs = sm + hp * HP_Q;
            __nv_bfloat16* Ks = sm + (2 + hp) * HP_Q;
            ush* VtH = (ush*)(sm + 4 * HP_Q) + hp * HP_V;
#pragma unroll
            for (int u = 0; u < 6; ++u) {
                unsigned dq = (unsigned)__cvta_generic_to_shared(Qs + tid * PQ + u * 8);
                CP16(dq, q3 + qsrc * 48 + u * 8);
                unsigned dk = (unsigned)__cvta_generic_to_shared(Ks + tid * PQ + u * 8);
                CP16(dk, k3 + tid * 48 + u * 8);
            }
#pragma unroll
            for (int u = 0; u < 2; ++u) {
                int ch = tid + u * 128;
                unsigned dv = (unsigned)__cvta_generic_to_shared(
                    VtH + (ch >> 4) * PVH + (ch & 15) * 8);
                CP16(dv, vt + (ch >> 4) * 128 + (ch & 15) * 8);
            }
        }
        asm volatile("cp.async.commit_group;");
        asm volatile("cp.async.wait_group 0;");
    }
    __syncthreads();

    const int g = lane >> 2, tg = lane & 3;
    const int r0 = wid * 32;
    const int a_row = lane & 15, a_col = (lane >> 4) * 8;
    const int bq = lane >> 3;
    const int b_rsub = ((bq >> 1) * 8) + (lane & 7);
    const int b_col8 = (bq & 1) * 8;

    const int nchunk = self ? 4 : 2;
    const int kb0 = (self || wid < 2) ? 0 : 64;
    const float4* mask_t = self
        ? (const float4*)(g_maskf + ((size_t)(b & 511) * 16 + wid * 4) * 1024)
        : (const float4*)(g_mmf + ((size_t)(b & 511) * 4 + (wid & 1) * 2) * 1024);

    float accO[2][2][2][4] = {};
    float rs[2][4] = {};

    for (int mc = 0; mc < nchunk; ++mc) {
        const int key0 = kb0 + mc * 32;
#pragma unroll
        for (int hp = 0; hp < 2; ++hp) {
            const __nv_bfloat16* Qs = sm + hp * HP_Q;
            const __nv_bfloat16* Ks = sm + (2 + hp) * HP_Q;
            const ush* VtH = (const ush*)(sm + 4 * HP_Q) + hp * HP_V;

            // bias fragments: mask (L1-hit for hp=1) + per-head rpe
            float4 f[8];
            {
                const float4* mt4 = mask_t + (size_t)mc * 256;
#pragma unroll
                for (int q = 0; q < 8; ++q) f[q] = mt4[q * 32 + lane];
                if (self) {
                    const float4* rt4 = (const float4*)(g_rpef +
                        ((size_t)(h0 + hp) * 16 + wid * 4) * 1024) + (size_t)mc * 256;
#pragma unroll
                    for (int q = 0; q < 8; ++q) {
                        float4 r = rt4[q * 32 + lane];
                        f[q].x += r.x; f[q].y += r.y; f[q].z += r.z; f[q].w += r.w;
                    }
                }
            }

            float accS[2][4][4] = {};
#pragma unroll
            for (int kt = 0; kt < 3; ++kt) {
                uint32_t aq[2][4], bf[2][4];
#pragma unroll
                for (int mt = 0; mt < 2; ++mt) {
                    unsigned ad = (unsigned)__cvta_generic_to_shared(
                        Qs + (r0 + mt * 16 + a_row) * PQ + kt * 16 + a_col);
                    LDSM4(aq[mt][0], aq[mt][1], aq[mt][2], aq[mt][3], ad);
                }
#pragma unroll
                for (int p = 0; p < 2; ++p) {
                    unsigned bd = (unsigned)__cvta_generic_to_shared(
                        Ks + (key0 + p * 16 + b_rsub) * PQ + kt * 16 + b_col8);
                    LDSM4(bf[p][0], bf[p][1], bf[p][2], bf[p][3], bd);
                }
#pragma unroll
                for (int mt = 0; mt < 2; ++mt)
#pragma unroll
                    for (int nt = 0; nt < 4; ++nt)
                        MMA_BF16(accS[mt][nt], aq[mt], bf[nt >> 1][(nt & 1) * 2],
                                 bf[nt >> 1][(nt & 1) * 2 + 1]);
            }
#pragma unroll
            for (int mt = 0; mt < 2; ++mt) {
#pragma unroll
                for (int nt = 0; nt < 4; ++nt) {
                    const float* f0 = (const float*)&f[mt * 4 + (nt >> 1)];
                    const float* f1 = (const float*)&f[mt * 4 + 2 + (nt >> 1)];
                    const int e0 = (nt & 1) * 2;
                    float p0 = __expf(accS[mt][nt][0] + f0[e0]);
                    float p1 = __expf(accS[mt][nt][1] + f0[e0 + 1]);
                    float p2 = __expf(accS[mt][nt][2] + f1[e0]);
                    float p3 = __expf(accS[mt][nt][3] + f1[e0 + 1]);
                    rs[hp][2 * mt]     += p0 + p1;
                    rs[hp][2 * mt + 1] += p2 + p3;
                    accS[mt][nt][0] = p0; accS[mt][nt][1] = p1;
                    accS[mt][nt][2] = p2; accS[mt][nt][3] = p3;
                }
            }
#pragma unroll
            for (int kt2 = 0; kt2 < 2; ++kt2) {
                uint32_t a2[2][4];
#pragma unroll
                for (int mt = 0; mt < 2; ++mt) {
                    CVT_F16X2(a2[mt][0], accS[mt][2 * kt2][1],     accS[mt][2 * kt2][0]);
                    CVT_F16X2(a2[mt][1], accS[mt][2 * kt2][3],     accS[mt][2 * kt2][2]);
                    CVT_F16X2(a2[mt][2], accS[mt][2 * kt2 + 1][1], accS[mt][2 * kt2 + 1][0]);
                    CVT_F16X2(a2[mt][3], accS[mt][2 * kt2 + 1][3], accS[mt][2 * kt2 + 1][2]);
                }
                uint32_t b2[4];
                unsigned bd = (unsigned)__cvta_generic_to_shared(
                    VtH + b_rsub * PVH + key0 + kt2 * 16 + b_col8);
                LDSM4(b2[0], b2[1], b2[2], b2[3], bd);
#pragma unroll
                for (int mt = 0; mt < 2; ++mt) {
                    MMA_F16(accO[hp][mt][0], a2[mt], b2[0], b2[1]);
                    MMA_F16(accO[hp][mt][1], a2[mt], b2[2], b2[3]);
                }
            }
        }
    }

#pragma unroll
    for (int hp = 0; hp < 2; ++hp)
#pragma unroll
        for (int s = 0; s < 4; ++s) {
            rs[hp][s] += __shfl_xor_sync(0xffffffffu, rs[hp][s], 1);
            rs[hp][s] += __shfl_xor_sync(0xffffffffu, rs[hp][s], 2);
        }

    const int cb2 = self ? 256 : 0;
#pragma unroll
    for (int hp = 0; hp < 2; ++hp) {
        const int h = h0 + hp;
        float i0 = 1.f / rs[hp][0], i1 = 1.f / rs[hp][1];
        float i2 = 1.f / rs[hp][2], i3 = 1.f / rs[hp][3];
#pragma unroll
        for (int mt = 0; mt < 2; ++mt) {
            float ia = mt ? i2 : i0, ib = mt ? i3 : i1;
#pragma unroll
            for (int nt2 = 0; nt2 < 2; ++nt2) {
                const int d0 = nt2 * 8 + 2 * tg;
                const int rA = r0 + mt * 16 + g;
                unsigned* oA = (unsigned*)(g_concat2h +
                    ((size_t)b * NTOK + rA) * 512 + cb2 + 2 * (h * HD + d0));
                oA[0] = dup_h(accO[hp][mt][nt2][0] * ia);
                oA[1] = dup_h(accO[hp][mt][nt2][1] * ia);
                unsigned* oB = (unsigned*)(g_concat2h +
                    ((size_t)b * NTOK + rA + 8) * 512 + cb2 + 2 * (h * HD + d0));
                oB[0] = dup_h(accO[hp][mt][nt2][2] * ib);
                oB[1] = dup_h(accO[hp][mt][nt2][3] * ib);
            }
        }
    }
}

// ---------------- launch ----------------------------------------------------
extern "C" void kernel_launch(void* const* d_in, const int* in_sizes, int n_in,
                              void* d_out, int out_size)
{
    const float* x         = (const float*)d_in[0];
    const float* mask      = (const float*)d_in[1];
    const float* w_self    = (const float*)d_in[2];
    const float* w_mut     = (const float*)d_in[3];
    const float* w_proj    = (const float*)d_in[4];
    const float* b_proj    = (const float*)d_in[5];
    const float* rpe_table = (const float*)d_in[6];
    const float* pe        = (const float*)d_in[7];
    const int*   rpe_index = (const int*)d_in[8];
    float* out = (float*)d_out;

    ush *cc, *wp;
    cudaGetSymbolAddress((void**)&wp, g_wp2);
    cudaGetSymbolAddress((void**)&cc, g_concat2h);

    const int SMEM = 2 * NSTAGE * STAGE_ELEMS * (int)sizeof(__nv_bfloat16); // 110592
    cudaFuncSetAttribute(qkv_all, cudaFuncAttributeMaxDynamicSharedMemorySize, SMEM);
    cudaFuncSetAttribute(proj_gemm, cudaFuncAttributeMaxDynamicSharedMemorySize, SMEM);
    cudaFuncSetAttribute(attn_tc, cudaFuncAttributeMaxDynamicSharedMemorySize, ATTN_SMEM);

    // launch 1: all prep
    prep_all<<<17504, 256>>>(x, pe, w_self, w_mut, w_proj, mask, rpe_index, rpe_table);

    // launch 2: merged QKV GEMMs (shared A in L2 across 6 col-blocks)
    qkv_all<<<dim3(6, 1024), 256, SMEM>>>();

    // launch 3: tensor-core attention (2 heads/block)
    attn_tc<<<dim3(WB, 8), 128, ATTN_SMEM>>>();

    // launch 4: projection (K' = 512, fp16)   (<- ncu capture slot)
    proj_gemm<<<dim3(1, 1024), 256, SMEM>>>(
        (const __nv_bfloat16*)cc, (const __nv_bfloat16*)wp, b_proj, out);
}